// round 5
// baseline (speedup 1.0000x reference)
#include <cuda_runtime.h>
#include <math_constants.h>

#define B_ 2
#define T_ 1024
#define M_ 1024
#define D_ 1024
#define H_ 16
#define L_ 2048
#define R_ 3072

// ---------------- scratch (allocation-free rule: __device__ globals) ----------------
__device__ float g_values[B_ * L_ * D_];        // [B, L, D]        16 MB
__device__ float g_q[B_ * H_ * T_ * 64];        // [B*H, T, 64]      8 MB
__device__ float g_k[B_ * H_ * L_ * 64];        // [B*H, L, 64]     16 MB
__device__ float g_v[B_ * H_ * L_ * 64];        // [B*H, L, 64]     16 MB
__device__ float g_rk[H_ * R_ * 64];            // [H, R, 64]       12 MB
__device__ float g_rel[B_ * H_ * T_ * L_];      // shifted rel [B*H, T, L] 256 MB
__device__ float g_attn[B_ * T_ * H_ * 64];     // [B*T, H*64]       8 MB

// ---------------- generic SGEMM: C[M x 1024] = A[M x 1024] @ W[1024 x 1024] --------
// BM=128, BN=64, BK=16, 256 threads (16x16), 8x4 microtile.
__device__ __forceinline__ void sgemm_body(
    const float* __restrict__ A, const float* __restrict__ W,
    float* __restrict__ C, int rowsPerBatch, bool headMode)
{
    __shared__ float As[16][128];
    __shared__ float Bs[16][64];
    const int tid = threadIdx.x;
    const int tx = tid & 15, ty = tid >> 4;
    const int row0 = blockIdx.y * 128;
    const int n0 = blockIdx.x * 64;

    float acc[8][4];
#pragma unroll
    for (int i = 0; i < 8; i++)
#pragma unroll
        for (int j = 0; j < 4; j++) acc[i][j] = 0.f;

    for (int k0 = 0; k0 < 1024; k0 += 16) {
#pragma unroll
        for (int u = 0; u < 2; u++) {
            int li = tid + u * 256;          // 0..511 float4 loads of A tile
            int m = li >> 2;                 // 0..127
            int kq = (li & 3) << 2;          // 0,4,8,12
            float4 a = *(const float4*)(A + (size_t)(row0 + m) * 1024 + k0 + kq);
            As[kq + 0][m] = a.x;
            As[kq + 1][m] = a.y;
            As[kq + 2][m] = a.z;
            As[kq + 3][m] = a.w;
        }
        {
            int kk = tid >> 4;
            int nq = (tid & 15) << 2;
            *(float4*)&Bs[kk][nq] = *(const float4*)(W + (size_t)(k0 + kk) * 1024 + n0 + nq);
        }
        __syncthreads();
#pragma unroll
        for (int kk = 0; kk < 16; kk++) {
            float4 a0 = *(const float4*)&As[kk][ty * 8];
            float4 a1 = *(const float4*)&As[kk][ty * 8 + 4];
            float4 b4 = *(const float4*)&Bs[kk][tx * 4];
            float av[8] = {a0.x, a0.y, a0.z, a0.w, a1.x, a1.y, a1.z, a1.w};
#pragma unroll
            for (int i = 0; i < 8; i++) {
                acc[i][0] += av[i] * b4.x;
                acc[i][1] += av[i] * b4.y;
                acc[i][2] += av[i] * b4.z;
                acc[i][3] += av[i] * b4.w;
            }
        }
        __syncthreads();
    }
#pragma unroll
    for (int i = 0; i < 8; i++) {
        int row = row0 + ty * 8 + i;
        int col = n0 + tx * 4;
        float4 o4 = make_float4(acc[i][0], acc[i][1], acc[i][2], acc[i][3]);
        if (headMode) {
            int b = row / rowsPerBatch;
            int tr = row - b * rowsPerBatch;
            int h = col >> 6;
            int d = col & 63;
            *(float4*)(C + ((((size_t)b * H_ + h) * rowsPerBatch + tr) << 6) + d) = o4;
        } else {
            *(float4*)(C + (size_t)row * 1024 + col) = o4;
        }
    }
}

__global__ __launch_bounds__(256) void k_proj_q(const float* __restrict__ A, const float* __restrict__ W)
{ sgemm_body(A, W, g_q, T_, true); }
__global__ __launch_bounds__(256) void k_proj_k(const float* __restrict__ W)
{ sgemm_body(g_values, W, g_k, L_, true); }
__global__ __launch_bounds__(256) void k_proj_v(const float* __restrict__ W)
{ sgemm_body(g_values, W, g_v, L_, true); }
__global__ __launch_bounds__(256) void k_proj_r(const float* __restrict__ A, const float* __restrict__ W)
{ sgemm_body(A, W, g_rk, R_, true); }
__global__ __launch_bounds__(256) void k_out(const float* __restrict__ W, float* __restrict__ out)
{ sgemm_body(g_attn, W, out, 1, false); }

// ---------------- concat: values = [memory ; inputs] -------------------------------
__global__ __launch_bounds__(256) void k_concat(
    const float* __restrict__ mem, const float* __restrict__ inp)
{
    size_t i4 = (size_t)blockIdx.x * blockDim.x + threadIdx.x;   // float4 index
    size_t e = i4 * 4;                                           // element index
    int b = (int)(e >> 21);                 // L*D = 2^21
    size_t rem = e & ((1u << 21) - 1);
    int l = (int)(rem >> 10);               // D = 2^10
    int d = (int)(rem & 1023);
    float4 val;
    if (l < M_) val = *(const float4*)(mem + ((size_t)b * M_ + l) * 1024 + d);
    else        val = *(const float4*)(inp + ((size_t)b * T_ + (l - M_)) * 1024 + d);
    *(float4*)(g_values + e) = val;
}

// ---------------- rel GEMM, banded, written in shifted layout ----------------------
// rel[b,h,t,r] = (q[b,t,h,:]+rrb[h,:]) . rk[r,h,:];  shifted[t,j] = rel[t, T - t + j]
// We write shifted[t,j] directly (j = r - T + t), skipping tiles fully outside band.
__global__ __launch_bounds__(256) void k_relgemm(const float* __restrict__ rrb)
{
    const int r0 = blockIdx.x * 64;
    const int t0 = blockIdx.y * 64;
    // tile needed iff r-range [r0, r0+63] intersects [T - t0 - 63, T - t0 + L - 1]
    if (r0 + 63 < T_ - t0 - 63 || r0 > T_ - t0 + L_ - 1) return;
    const int bh = blockIdx.z;
    const int h = bh & (H_ - 1);

    __shared__ float Qt[64 * 64];   // [d][t]
    __shared__ float Rt[64 * 64];   // [d][r]
    const int tid = threadIdx.x;
    const int tx = tid & 15, ty = tid >> 4;

#pragma unroll
    for (int u = 0; u < 4; u++) {
        int li = tid + u * 256;
        int row = li & 63;
        int dq = (li >> 6) << 2;
        float4 qv = *(const float4*)(g_q + (((size_t)bh * T_ + t0 + row) << 6) + dq);
        float4 bv = *(const float4*)(rrb + h * 64 + dq);
        Qt[(dq + 0) * 64 + row] = qv.x + bv.x;
        Qt[(dq + 1) * 64 + row] = qv.y + bv.y;
        Qt[(dq + 2) * 64 + row] = qv.z + bv.z;
        Qt[(dq + 3) * 64 + row] = qv.w + bv.w;
        float4 rv = *(const float4*)(g_rk + (((size_t)h * R_ + r0 + row) << 6) + dq);
        Rt[(dq + 0) * 64 + row] = rv.x;
        Rt[(dq + 1) * 64 + row] = rv.y;
        Rt[(dq + 2) * 64 + row] = rv.z;
        Rt[(dq + 3) * 64 + row] = rv.w;
    }
    __syncthreads();

    float acc[4][4];
#pragma unroll
    for (int i = 0; i < 4; i++)
#pragma unroll
        for (int j = 0; j < 4; j++) acc[i][j] = 0.f;

#pragma unroll
    for (int d = 0; d < 64; d++) {
        float4 a = *(const float4*)&Qt[d * 64 + ty * 4];
        float4 r4 = *(const float4*)&Rt[d * 64 + tx * 4];
        float aa[4] = {a.x, a.y, a.z, a.w};
        float rr[4] = {r4.x, r4.y, r4.z, r4.w};
#pragma unroll
        for (int i = 0; i < 4; i++)
#pragma unroll
            for (int j = 0; j < 4; j++) acc[i][j] += aa[i] * rr[j];
    }

#pragma unroll
    for (int i = 0; i < 4; i++) {
        int t = t0 + ty * 4 + i;
        size_t rowbase = ((size_t)bh * T_ + t) * (size_t)L_;
#pragma unroll
        for (int jj = 0; jj < 4; jj++) {
            int j = r0 + tx * 4 + jj - T_ + t;   // shifted column
            if (j >= 0 && j < L_) g_rel[rowbase + j] = acc[i][jj];
        }
    }
}

// ---------------- fused flash attention: content + rel + softmax + PV --------------
#define FLASH_SMEM ((3 * 4096 + 64 * 68) * 4)

__global__ __launch_bounds__(256) void k_flash(
    const float* __restrict__ mask, const float* __restrict__ rwb)
{
    extern __shared__ float sm[];
    float* Qt = sm;            // [d][t]  64x64
    float* Kt = sm + 4096;     // [d][j]  64x64
    float* Vs = sm + 8192;     // [j][d]  64x64
    float* Ps = sm + 12288;    // [t][j]  64x68 (padded)

    const int tid = threadIdx.x;
    const int tx = tid & 15, ty = tid >> 4;
    const int t0 = blockIdx.x * 64;
    const int h = blockIdx.y;
    const int b = blockIdx.z;
    const int bh = b * H_ + h;

    // Q tile transposed, + r_w_bias
#pragma unroll
    for (int u = 0; u < 4; u++) {
        int li = tid + u * 256;
        int row = li & 63;
        int dq = (li >> 6) << 2;
        float4 qv = *(const float4*)(g_q + (((size_t)bh * T_ + t0 + row) << 6) + dq);
        float4 bv = *(const float4*)(rwb + h * 64 + dq);
        Qt[(dq + 0) * 64 + row] = qv.x + bv.x;
        Qt[(dq + 1) * 64 + row] = qv.y + bv.y;
        Qt[(dq + 2) * 64 + row] = qv.z + bv.z;
        Qt[(dq + 3) * 64 + row] = qv.w + bv.w;
    }

    float m_i[4], l_i[4], o[4][4];
#pragma unroll
    for (int i = 0; i < 4; i++) {
        m_i[i] = -CUDART_INF_F;
        l_i[i] = 0.f;
#pragma unroll
        for (int c = 0; c < 4; c++) o[i][c] = 0.f;
    }

    for (int j0 = 0; j0 < L_; j0 += 64) {
        // K transposed (lane-varies-row mapping: conflict-free STS)
#pragma unroll
        for (int u = 0; u < 4; u++) {
            int li = tid + u * 256;
            int row = li & 63;
            int dq = (li >> 6) << 2;
            float4 kv = *(const float4*)(g_k + (((size_t)bh * L_ + j0 + row) << 6) + dq);
            Kt[(dq + 0) * 64 + row] = kv.x;
            Kt[(dq + 1) * 64 + row] = kv.y;
            Kt[(dq + 2) * 64 + row] = kv.z;
            Kt[(dq + 3) * 64 + row] = kv.w;
        }
        // V natural (coalesced float4 copy)
#pragma unroll
        for (int u = 0; u < 4; u++) {
            int li = tid + u * 256;
            int row = li >> 4;
            int dq = (li & 15) << 2;
            *(float4*)&Vs[row * 64 + dq] =
                *(const float4*)(g_v + (((size_t)bh * L_ + j0 + row) << 6) + dq);
        }
        __syncthreads();

        // S = Qw . K^T
        float s[4][4];
#pragma unroll
        for (int i = 0; i < 4; i++)
#pragma unroll
            for (int jj = 0; jj < 4; jj++) s[i][jj] = 0.f;
#pragma unroll
        for (int d = 0; d < 64; d++) {
            float4 a = *(const float4*)&Qt[d * 64 + ty * 4];
            float4 kx = *(const float4*)&Kt[d * 64 + tx * 4];
            float aa[4] = {a.x, a.y, a.z, a.w};
            float kk[4] = {kx.x, kx.y, kx.z, kx.w};
#pragma unroll
            for (int i = 0; i < 4; i++)
#pragma unroll
                for (int jj = 0; jj < 4; jj++) s[i][jj] += aa[i] * kk[jj];
        }

        // + rel (pre-shifted), * DK^-0.5, mask
#pragma unroll
        for (int i = 0; i < 4; i++) {
            int t = t0 + ty * 4 + i;
            float4 rv = *(const float4*)(g_rel + ((size_t)bh * T_ + t) * (size_t)L_ + j0 + tx * 4);
            float4 mv = *(const float4*)(mask + ((size_t)b * T_ + t) * (size_t)L_ + j0 + tx * 4);
            s[i][0] = (s[i][0] + rv.x) * 0.125f - (1.f - mv.x) * 1e30f;
            s[i][1] = (s[i][1] + rv.y) * 0.125f - (1.f - mv.y) * 1e30f;
            s[i][2] = (s[i][2] + rv.z) * 0.125f - (1.f - mv.z) * 1e30f;
            s[i][3] = (s[i][3] + rv.w) * 0.125f - (1.f - mv.w) * 1e30f;
        }

        // online softmax (row = 16 consecutive lanes, xor-shuffle reduce)
#pragma unroll
        for (int i = 0; i < 4; i++) {
            float mx = fmaxf(fmaxf(s[i][0], s[i][1]), fmaxf(s[i][2], s[i][3]));
#pragma unroll
            for (int off = 8; off > 0; off >>= 1)
                mx = fmaxf(mx, __shfl_xor_sync(0xffffffffu, mx, off));
            float mn = fmaxf(m_i[i], mx);
            float alpha = __expf(m_i[i] - mn);
            float rs = 0.f;
#pragma unroll
            for (int jj = 0; jj < 4; jj++) {
                float p = __expf(s[i][jj] - mn);
                s[i][jj] = p;
                rs += p;
            }
#pragma unroll
            for (int off = 8; off > 0; off >>= 1)
                rs += __shfl_xor_sync(0xffffffffu, rs, off);
            m_i[i] = mn;
            l_i[i] = l_i[i] * alpha + rs;
            o[i][0] *= alpha; o[i][1] *= alpha; o[i][2] *= alpha; o[i][3] *= alpha;
        }

        // P -> smem (float4, own region; prev iter's readers done at loop-end sync)
#pragma unroll
        for (int i = 0; i < 4; i++) {
            *(float4*)&Ps[(ty * 4 + i) * 68 + tx * 4] =
                make_float4(s[i][0], s[i][1], s[i][2], s[i][3]);
        }
        __syncthreads();

        // O += P @ V
#pragma unroll 16
        for (int j = 0; j < 64; j++) {
            float4 vv = *(const float4*)&Vs[j * 64 + tx * 4];
#pragma unroll
            for (int i = 0; i < 4; i++) {
                float p = Ps[(ty * 4 + i) * 68 + j];
                o[i][0] += p * vv.x;
                o[i][1] += p * vv.y;
                o[i][2] += p * vv.z;
                o[i][3] += p * vv.w;
            }
        }
        __syncthreads();
    }

    // normalize + write attn in [B*T, H*64] for the output GEMM
#pragma unroll
    for (int i = 0; i < 4; i++) {
        int t = t0 + ty * 4 + i;
        float inv = 1.f / l_i[i];
        *(float4*)(g_attn + (((size_t)b * T_ + t) << 10) + h * 64 + tx * 4) =
            make_float4(o[i][0] * inv, o[i][1] * inv, o[i][2] * inv, o[i][3] * inv);
    }
}

// ---------------- launch ------------------------------------------------------------
extern "C" void kernel_launch(void* const* d_in, const int* in_sizes, int n_in,
                              void* d_out, int out_size)
{
    (void)in_sizes; (void)n_in; (void)out_size;
    const float* inputs = (const float*)d_in[0];
    const float* mask   = (const float*)d_in[1];
    const float* pos    = (const float*)d_in[2];
    const float* mem    = (const float*)d_in[3];
    const float* Wq     = (const float*)d_in[4];
    const float* Wk     = (const float*)d_in[5];
    const float* Wv     = (const float*)d_in[6];
    const float* Wr     = (const float*)d_in[7];
    const float* rwb    = (const float*)d_in[8];
    const float* rrb    = (const float*)d_in[9];
    const float* Wout   = (const float*)d_in[10];
    float* out = (float*)d_out;

    cudaFuncSetAttribute(k_flash, cudaFuncAttributeMaxDynamicSharedMemorySize, FLASH_SMEM);

    k_concat<<<(B_ * L_ * D_ / 4) / 256, 256>>>(mem, inputs);

    k_proj_q<<<dim3(16, (B_ * T_) / 128), 256>>>(inputs, Wq);      // [2048 x 1024]
    k_proj_k<<<dim3(16, (B_ * L_) / 128), 256>>>(Wk);              // [4096 x 1024]
    k_proj_v<<<dim3(16, (B_ * L_) / 128), 256>>>(Wv);              // [4096 x 1024]
    k_proj_r<<<dim3(16, R_ / 128), 256>>>(pos, Wr);                // [3072 x 1024]

    k_relgemm<<<dim3(R_ / 64, T_ / 64, B_ * H_), 256>>>(rrb);      // banded rel

    k_flash<<<dim3(T_ / 64, H_, B_), 256, FLASH_SMEM>>>(mask, rwb);

    k_out<<<dim3(16, (B_ * T_) / 128), 256>>>(Wout, out);          // [2048 x 1024]
}

// round 7
// speedup vs baseline: 1.5679x; 1.5679x over previous
#include <cuda_runtime.h>
#include <math_constants.h>

#define B_ 2
#define T_ 1024
#define M_ 1024
#define D_ 1024
#define H_ 16
#define L_ 2048
#define R_ 3072

// ---------------- scratch (allocation-free rule: __device__ globals) ----------------
__device__ float g_values[B_ * L_ * D_];        // [B, L, D]
__device__ float g_q[B_ * H_ * T_ * 64];        // [B*H, T, 64]
__device__ float g_k[B_ * H_ * L_ * 64];        // [B*H, L, 64]
__device__ float g_v[B_ * H_ * L_ * 64];        // [B*H, L, 64]
__device__ float g_rk[H_ * R_ * 64];            // [H, R, 64]
__device__ float g_rel[B_ * H_ * T_ * L_];      // shifted rel [B*H, T, L]
__device__ float g_attn[B_ * T_ * H_ * 64];     // [B*T, H*64]

// ---------------- tf32 mma helpers -------------------------------------------------
__device__ __forceinline__ unsigned f2tf(float f) {
    unsigned u;
    asm("cvt.rna.tf32.f32 %0, %1;" : "=r"(u) : "f"(f));
    return u;
}

__device__ __forceinline__ void mma_tf32(float* c, const unsigned* a, const unsigned* b) {
    asm volatile(
        "mma.sync.aligned.m16n8k8.row.col.f32.tf32.tf32.f32 "
        "{%0,%1,%2,%3}, {%4,%5,%6,%7}, {%8,%9}, {%0,%1,%2,%3};"
        : "+f"(c[0]), "+f"(c[1]), "+f"(c[2]), "+f"(c[3])
        : "r"(a[0]), "r"(a[1]), "r"(a[2]), "r"(a[3]), "r"(b[0]), "r"(b[1]));
}

// ---------------- tf32 GEMM: C[rows x 1024] = A[rows x 1024] @ W[1024 x 1024] ------
// BM=128, BN=128, BK=16. 256 threads = 8 warps in 2(M)x4(N); warp tile 64x32.
#define AS_STRIDE 20
#define BS_STRIDE 136

__device__ __forceinline__ void gemm_tf32_body(
    const float* __restrict__ A, const float* __restrict__ W,
    float* __restrict__ C, int rowsPerBatch, bool headMode)
{
    __shared__ unsigned As[128 * AS_STRIDE];   // [row][k]
    __shared__ unsigned Bs[16 * BS_STRIDE];    // [k][col]

    const int tid = threadIdx.x;
    const int lane = tid & 31, warp = tid >> 5;
    const int wm = (warp & 1) * 64, wn = (warp >> 1) * 32;
    const int gid = lane >> 2, tig = lane & 3;
    const int row0 = blockIdx.y * 128;
    const int n0 = blockIdx.x * 128;

    float acc[4][4][4];
#pragma unroll
    for (int mt = 0; mt < 4; mt++)
#pragma unroll
        for (int nt = 0; nt < 4; nt++)
#pragma unroll
            for (int c = 0; c < 4; c++) acc[mt][nt][c] = 0.f;

    for (int k0 = 0; k0 < 1024; k0 += 16) {
        // stage A tile [128 x 16]
#pragma unroll
        for (int u = 0; u < 2; u++) {
            int idx = tid + u * 256;
            int r = idx >> 2, kq = (idx & 3) << 2;
            float4 a = *(const float4*)(A + (size_t)(row0 + r) * 1024 + k0 + kq);
            unsigned* dst = &As[r * AS_STRIDE + kq];
            dst[0] = f2tf(a.x); dst[1] = f2tf(a.y);
            dst[2] = f2tf(a.z); dst[3] = f2tf(a.w);
        }
        // stage W tile [16 x 128]
#pragma unroll
        for (int u = 0; u < 2; u++) {
            int idx = tid + u * 256;
            int kk = idx >> 5, c4 = (idx & 31) << 2;
            float4 w = *(const float4*)(W + (size_t)(k0 + kk) * 1024 + n0 + c4);
            unsigned* dst = &Bs[kk * BS_STRIDE + c4];
            dst[0] = f2tf(w.x); dst[1] = f2tf(w.y);
            dst[2] = f2tf(w.z); dst[3] = f2tf(w.w);
        }
        __syncthreads();

#pragma unroll
        for (int ks = 0; ks < 2; ks++) {
            const int kb = ks * 8;
            unsigned bfr[4][2];
#pragma unroll
            for (int nt = 0; nt < 4; nt++) {
                int col = wn + nt * 8 + gid;
                bfr[nt][0] = Bs[(kb + tig) * BS_STRIDE + col];
                bfr[nt][1] = Bs[(kb + tig + 4) * BS_STRIDE + col];
            }
#pragma unroll
            for (int mt = 0; mt < 4; mt++) {
                int row = wm + mt * 16 + gid;
                unsigned af[4];
                af[0] = As[row * AS_STRIDE + kb + tig];
                af[1] = As[(row + 8) * AS_STRIDE + kb + tig];
                af[2] = As[row * AS_STRIDE + kb + tig + 4];
                af[3] = As[(row + 8) * AS_STRIDE + kb + tig + 4];
#pragma unroll
                for (int nt = 0; nt < 4; nt++) mma_tf32(acc[mt][nt], af, bfr[nt]);
            }
        }
        __syncthreads();
    }

    // epilogue
#pragma unroll
    for (int mt = 0; mt < 4; mt++) {
#pragma unroll
        for (int nt = 0; nt < 4; nt++) {
            int rr = row0 + wm + mt * 16 + gid;
            int cc = n0 + wn + nt * 8 + 2 * tig;
#pragma unroll
            for (int half = 0; half < 2; half++) {
                int row = rr + half * 8;
                float2 o2 = make_float2(acc[mt][nt][half * 2], acc[mt][nt][half * 2 + 1]);
                if (headMode) {
                    int b = row / rowsPerBatch;
                    int tr = row - b * rowsPerBatch;
                    int h = cc >> 6;
                    int d = cc & 63;
                    *(float2*)(C + ((((size_t)b * H_ + h) * rowsPerBatch + tr) << 6) + d) = o2;
                } else {
                    *(float2*)(C + (size_t)row * 1024 + cc) = o2;
                }
            }
        }
    }
}

__global__ __launch_bounds__(256) void k_proj_q(const float* __restrict__ A, const float* __restrict__ W)
{ gemm_tf32_body(A, W, g_q, T_, true); }
__global__ __launch_bounds__(256) void k_proj_k(const float* __restrict__ W)
{ gemm_tf32_body(g_values, W, g_k, L_, true); }
__global__ __launch_bounds__(256) void k_proj_v(const float* __restrict__ W)
{ gemm_tf32_body(g_values, W, g_v, L_, true); }
__global__ __launch_bounds__(256) void k_proj_r(const float* __restrict__ A, const float* __restrict__ W)
{ gemm_tf32_body(A, W, g_rk, R_, true); }
__global__ __launch_bounds__(256) void k_out(const float* __restrict__ W, float* __restrict__ out)
{ gemm_tf32_body(g_attn, W, out, 1, false); }

// ---------------- concat: values = [memory ; inputs] -------------------------------
__global__ __launch_bounds__(256) void k_concat(
    const float* __restrict__ mem, const float* __restrict__ inp)
{
    size_t i4 = (size_t)blockIdx.x * blockDim.x + threadIdx.x;
    size_t e = i4 * 4;
    int b = (int)(e >> 21);
    size_t rem = e & ((1u << 21) - 1);
    int l = (int)(rem >> 10);
    int d = (int)(rem & 1023);
    float4 val;
    if (l < M_) val = *(const float4*)(mem + ((size_t)b * M_ + l) * 1024 + d);
    else        val = *(const float4*)(inp + ((size_t)b * T_ + (l - M_)) * 1024 + d);
    *(float4*)(g_values + e) = val;
}

// ---------------- rel GEMM (tf32 mma), banded, written in shifted layout -----------
// rel[b,h,t,r] = (q[b,t,h,:]+rrb[h,:]) . rk[r,h,:];  shifted[t,j] = rel[t, T - t + j]
#define RS_STRIDE 72

__global__ __launch_bounds__(256) void k_relgemm(const float* __restrict__ rrb)
{
    const int r0 = blockIdx.x * 64;
    const int t0 = blockIdx.y * 64;
    if (r0 + 63 < T_ - t0 - 63 || r0 > T_ - t0 + L_ - 1) return;
    const int bh = blockIdx.z;
    const int h = bh & (H_ - 1);

    __shared__ unsigned Qs[64 * RS_STRIDE];   // A operand: [t][d]
    __shared__ unsigned Rs[64 * RS_STRIDE];   // B operand (col-major k x n): [r][d]

    const int tid = threadIdx.x;
    const int lane = tid & 31, warp = tid >> 5;
    const int wm = (warp & 1) * 32, wn = (warp >> 1) * 16;
    const int gid = lane >> 2, tig = lane & 3;

    // stage tiles: 64x64 each, 4 float4 per thread
#pragma unroll
    for (int u = 0; u < 4; u++) {
        int idx = tid + u * 256;
        int row = idx >> 4, dq = (idx & 15) << 2;
        float4 qv = *(const float4*)(g_q + (((size_t)bh * T_ + t0 + row) << 6) + dq);
        float4 bv = *(const float4*)(rrb + h * 64 + dq);
        unsigned* qd = &Qs[row * RS_STRIDE + dq];
        qd[0] = f2tf(qv.x + bv.x); qd[1] = f2tf(qv.y + bv.y);
        qd[2] = f2tf(qv.z + bv.z); qd[3] = f2tf(qv.w + bv.w);
        float4 rv = *(const float4*)(g_rk + (((size_t)h * R_ + r0 + row) << 6) + dq);
        unsigned* rd = &Rs[row * RS_STRIDE + dq];
        rd[0] = f2tf(rv.x); rd[1] = f2tf(rv.y);
        rd[2] = f2tf(rv.z); rd[3] = f2tf(rv.w);
    }
    __syncthreads();

    float acc[2][2][4];
#pragma unroll
    for (int mt = 0; mt < 2; mt++)
#pragma unroll
        for (int nt = 0; nt < 2; nt++)
#pragma unroll
            for (int c = 0; c < 4; c++) acc[mt][nt][c] = 0.f;

#pragma unroll
    for (int ks = 0; ks < 8; ks++) {
        const int kb = ks * 8;
        unsigned bfr[2][2];
#pragma unroll
        for (int nt = 0; nt < 2; nt++) {
            int col = wn + nt * 8 + gid;
            bfr[nt][0] = Rs[col * RS_STRIDE + kb + tig];
            bfr[nt][1] = Rs[col * RS_STRIDE + kb + tig + 4];
        }
#pragma unroll
        for (int mt = 0; mt < 2; mt++) {
            int row = wm + mt * 16 + gid;
            unsigned af[4];
            af[0] = Qs[row * RS_STRIDE + kb + tig];
            af[1] = Qs[(row + 8) * RS_STRIDE + kb + tig];
            af[2] = Qs[row * RS_STRIDE + kb + tig + 4];
            af[3] = Qs[(row + 8) * RS_STRIDE + kb + tig + 4];
#pragma unroll
            for (int nt = 0; nt < 2; nt++) mma_tf32(acc[mt][nt], af, bfr[nt]);
        }
    }

    // epilogue: shifted column j = r - T + t, bounds-checked
#pragma unroll
    for (int mt = 0; mt < 2; mt++) {
#pragma unroll
        for (int nt = 0; nt < 2; nt++) {
            int rbase = r0 + wn + nt * 8 + 2 * tig;
#pragma unroll
            for (int half = 0; half < 2; half++) {
                int t = t0 + wm + mt * 16 + gid + half * 8;
                size_t rowbase = ((size_t)bh * T_ + t) * (size_t)L_;
                int j0 = rbase - T_ + t;
                if (j0 >= 0 && j0 < L_) g_rel[rowbase + j0] = acc[mt][nt][half * 2];
                int j1 = j0 + 1;
                if (j1 >= 0 && j1 < L_) g_rel[rowbase + j1] = acc[mt][nt][half * 2 + 1];
            }
        }
    }
}

// ---------------- fused flash attention: content + rel + softmax + PV --------------
#define FLASH_SMEM ((3 * 4096 + 64 * 68) * 4)

__global__ __launch_bounds__(256) void k_flash(
    const float* __restrict__ mask, const float* __restrict__ rwb)
{
    extern __shared__ float sm[];
    float* Qt = sm;            // [d][t]  64x64
    float* Kt = sm + 4096;     // [d][j]  64x64
    float* Vs = sm + 8192;     // [j][d]  64x64
    float* Ps = sm + 12288;    // [t][j]  64x68 (padded)

    const int tid = threadIdx.x;
    const int tx = tid & 15, ty = tid >> 4;
    const int t0 = blockIdx.x * 64;
    const int h = blockIdx.y;
    const int b = blockIdx.z;
    const int bh = b * H_ + h;

#pragma unroll
    for (int u = 0; u < 4; u++) {
        int li = tid + u * 256;
        int row = li & 63;
        int dq = (li >> 6) << 2;
        float4 qv = *(const float4*)(g_q + (((size_t)bh * T_ + t0 + row) << 6) + dq);
        float4 bv = *(const float4*)(rwb + h * 64 + dq);
        Qt[(dq + 0) * 64 + row] = qv.x + bv.x;
        Qt[(dq + 1) * 64 + row] = qv.y + bv.y;
        Qt[(dq + 2) * 64 + row] = qv.z + bv.z;
        Qt[(dq + 3) * 64 + row] = qv.w + bv.w;
    }

    float m_i[4], l_i[4], o[4][4];
#pragma unroll
    for (int i = 0; i < 4; i++) {
        m_i[i] = -CUDART_INF_F;
        l_i[i] = 0.f;
#pragma unroll
        for (int c = 0; c < 4; c++) o[i][c] = 0.f;
    }

    for (int j0 = 0; j0 < L_; j0 += 64) {
#pragma unroll
        for (int u = 0; u < 4; u++) {
            int li = tid + u * 256;
            int row = li & 63;
            int dq = (li >> 6) << 2;
            float4 kv = *(const float4*)(g_k + (((size_t)bh * L_ + j0 + row) << 6) + dq);
            Kt[(dq + 0) * 64 + row] = kv.x;
            Kt[(dq + 1) * 64 + row] = kv.y;
            Kt[(dq + 2) * 64 + row] = kv.z;
            Kt[(dq + 3) * 64 + row] = kv.w;
        }
#pragma unroll
        for (int u = 0; u < 4; u++) {
            int li = tid + u * 256;
            int row = li >> 4;
            int dq = (li & 15) << 2;
            *(float4*)&Vs[row * 64 + dq] =
                *(const float4*)(g_v + (((size_t)bh * L_ + j0 + row) << 6) + dq);
        }
        __syncthreads();

        float s[4][4];
#pragma unroll
        for (int i = 0; i < 4; i++)
#pragma unroll
            for (int jj = 0; jj < 4; jj++) s[i][jj] = 0.f;
#pragma unroll
        for (int d = 0; d < 64; d++) {
            float4 a = *(const float4*)&Qt[d * 64 + ty * 4];
            float4 kx = *(const float4*)&Kt[d * 64 + tx * 4];
            float aa[4] = {a.x, a.y, a.z, a.w};
            float kk[4] = {kx.x, kx.y, kx.z, kx.w};
#pragma unroll
            for (int i = 0; i < 4; i++)
#pragma unroll
                for (int jj = 0; jj < 4; jj++) s[i][jj] += aa[i] * kk[jj];
        }

#pragma unroll
        for (int i = 0; i < 4; i++) {
            int t = t0 + ty * 4 + i;
            float4 rv = *(const float4*)(g_rel + ((size_t)bh * T_ + t) * (size_t)L_ + j0 + tx * 4);
            float4 mv = *(const float4*)(mask + ((size_t)b * T_ + t) * (size_t)L_ + j0 + tx * 4);
            s[i][0] = (s[i][0] + rv.x) * 0.125f - (1.f - mv.x) * 1e30f;
            s[i][1] = (s[i][1] + rv.y) * 0.125f - (1.f - mv.y) * 1e30f;
            s[i][2] = (s[i][2] + rv.z) * 0.125f - (1.f - mv.z) * 1e30f;
            s[i][3] = (s[i][3] + rv.w) * 0.125f - (1.f - mv.w) * 1e30f;
        }

#pragma unroll
        for (int i = 0; i < 4; i++) {
            float mx = fmaxf(fmaxf(s[i][0], s[i][1]), fmaxf(s[i][2], s[i][3]));
#pragma unroll
            for (int off = 8; off > 0; off >>= 1)
                mx = fmaxf(mx, __shfl_xor_sync(0xffffffffu, mx, off));
            float mn = fmaxf(m_i[i], mx);
            float alpha = __expf(m_i[i] - mn);
            float rs = 0.f;
#pragma unroll
            for (int jj = 0; jj < 4; jj++) {
                float p = __expf(s[i][jj] - mn);
                s[i][jj] = p;
                rs += p;
            }
#pragma unroll
            for (int off = 8; off > 0; off >>= 1)
                rs += __shfl_xor_sync(0xffffffffu, rs, off);
            m_i[i] = mn;
            l_i[i] = l_i[i] * alpha + rs;
            o[i][0] *= alpha; o[i][1] *= alpha; o[i][2] *= alpha; o[i][3] *= alpha;
        }

#pragma unroll
        for (int i = 0; i < 4; i++) {
            *(float4*)&Ps[(ty * 4 + i) * 68 + tx * 4] =
                make_float4(s[i][0], s[i][1], s[i][2], s[i][3]);
        }
        __syncthreads();

#pragma unroll 16
        for (int j = 0; j < 64; j++) {
            float4 vv = *(const float4*)&Vs[j * 64 + tx * 4];
#pragma unroll
            for (int i = 0; i < 4; i++) {
                float p = Ps[(ty * 4 + i) * 68 + j];
                o[i][0] += p * vv.x;
                o[i][1] += p * vv.y;
                o[i][2] += p * vv.z;
                o[i][3] += p * vv.w;
            }
        }
        __syncthreads();
    }

#pragma unroll
    for (int i = 0; i < 4; i++) {
        int t = t0 + ty * 4 + i;
        float inv = 1.f / l_i[i];
        *(float4*)(g_attn + (((size_t)b * T_ + t) << 10) + h * 64 + tx * 4) =
            make_float4(o[i][0] * inv, o[i][1] * inv, o[i][2] * inv, o[i][3] * inv);
    }
}

// ---------------- launch ------------------------------------------------------------
extern "C" void kernel_launch(void* const* d_in, const int* in_sizes, int n_in,
                              void* d_out, int out_size)
{
    (void)in_sizes; (void)n_in; (void)out_size;
    const float* inputs = (const float*)d_in[0];
    const float* mask   = (const float*)d_in[1];
    const float* pos    = (const float*)d_in[2];
    const float* mem    = (const float*)d_in[3];
    const float* Wq     = (const float*)d_in[4];
    const float* Wk     = (const float*)d_in[5];
    const float* Wv     = (const float*)d_in[6];
    const float* Wr     = (const float*)d_in[7];
    const float* rwb    = (const float*)d_in[8];
    const float* rrb    = (const float*)d_in[9];
    const float* Wout   = (const float*)d_in[10];
    float* out = (float*)d_out;

    cudaFuncSetAttribute(k_flash, cudaFuncAttributeMaxDynamicSharedMemorySize, FLASH_SMEM);

    k_concat<<<(B_ * L_ * D_ / 4) / 256, 256>>>(mem, inputs);

    k_proj_q<<<dim3(8, (B_ * T_) / 128), 256>>>(inputs, Wq);
    k_proj_k<<<dim3(8, (B_ * L_) / 128), 256>>>(Wk);
    k_proj_v<<<dim3(8, (B_ * L_) / 128), 256>>>(Wv);
    k_proj_r<<<dim3(8, R_ / 128), 256>>>(pos, Wr);

    k_relgemm<<<dim3(R_ / 64, T_ / 64, B_ * H_), 256>>>(rrb);

    k_flash<<<dim3(T_ / 64, H_, B_), 256, FLASH_SMEM>>>(mask, rwb);

    k_out<<<dim3(8, (B_ * T_) / 128), 256>>>(Wout, out);
}

// round 8
// speedup vs baseline: 2.0965x; 1.3372x over previous
#include <cuda_runtime.h>
#include <math_constants.h>

#define B_ 2
#define T_ 1024
#define M_ 1024
#define D_ 1024
#define H_ 16
#define L_ 2048
#define R_ 3072

// ---------------- scratch (allocation-free rule: __device__ globals) ----------------
__device__ float g_values[B_ * L_ * D_];        // [B, L, D]
__device__ float g_q[B_ * H_ * T_ * 64];        // [B*H, T, 64]
__device__ float g_k[B_ * H_ * L_ * 64];        // [B*H, L, 64]
__device__ float g_v[B_ * H_ * L_ * 64];        // [B*H, L, 64]
__device__ float g_rk[H_ * R_ * 64];            // [H, R, 64]
__device__ float g_rel[B_ * H_ * T_ * L_];      // shifted rel [B*H, T, L]
__device__ float g_attn[B_ * T_ * H_ * 64];     // [B*T, H*64]

// ---------------- tf32 mma helpers -------------------------------------------------
__device__ __forceinline__ unsigned f2tf(float f) {
    unsigned u;
    asm("cvt.rna.tf32.f32 %0, %1;" : "=r"(u) : "f"(f));
    return u;
}

__device__ __forceinline__ void mma_tf32(float* c, const unsigned* a, const unsigned* b) {
    asm volatile(
        "mma.sync.aligned.m16n8k8.row.col.f32.tf32.tf32.f32 "
        "{%0,%1,%2,%3}, {%4,%5,%6,%7}, {%8,%9}, {%0,%1,%2,%3};"
        : "+f"(c[0]), "+f"(c[1]), "+f"(c[2]), "+f"(c[3])
        : "r"(a[0]), "r"(a[1]), "r"(a[2]), "r"(a[3]), "r"(b[0]), "r"(b[1]));
}

// ---------------- tf32 GEMM: C[rows x 1024] = A[rows x 1024] @ W[1024 x 1024] ------
// BM=128, BN=128, BK=16. 256 threads = 8 warps in 2(M)x4(N); warp tile 64x32.
#define AS_STRIDE 20
#define BS_STRIDE 136

__device__ __forceinline__ void gemm_tf32_body(
    const float* __restrict__ A, const float* __restrict__ W,
    float* __restrict__ C, int rowsPerBatch, bool headMode)
{
    __shared__ unsigned As[128 * AS_STRIDE];   // [row][k]
    __shared__ unsigned Bs[16 * BS_STRIDE];    // [k][col]

    const int tid = threadIdx.x;
    const int lane = tid & 31, warp = tid >> 5;
    const int wm = (warp & 1) * 64, wn = (warp >> 1) * 32;
    const int gid = lane >> 2, tig = lane & 3;
    const int row0 = blockIdx.y * 128;
    const int n0 = blockIdx.x * 128;

    float acc[4][4][4];
#pragma unroll
    for (int mt = 0; mt < 4; mt++)
#pragma unroll
        for (int nt = 0; nt < 4; nt++)
#pragma unroll
            for (int c = 0; c < 4; c++) acc[mt][nt][c] = 0.f;

    for (int k0 = 0; k0 < 1024; k0 += 16) {
#pragma unroll
        for (int u = 0; u < 2; u++) {
            int idx = tid + u * 256;
            int r = idx >> 2, kq = (idx & 3) << 2;
            float4 a = *(const float4*)(A + (size_t)(row0 + r) * 1024 + k0 + kq);
            unsigned* dst = &As[r * AS_STRIDE + kq];
            dst[0] = f2tf(a.x); dst[1] = f2tf(a.y);
            dst[2] = f2tf(a.z); dst[3] = f2tf(a.w);
        }
#pragma unroll
        for (int u = 0; u < 2; u++) {
            int idx = tid + u * 256;
            int kk = idx >> 5, c4 = (idx & 31) << 2;
            float4 w = *(const float4*)(W + (size_t)(k0 + kk) * 1024 + n0 + c4);
            unsigned* dst = &Bs[kk * BS_STRIDE + c4];
            dst[0] = f2tf(w.x); dst[1] = f2tf(w.y);
            dst[2] = f2tf(w.z); dst[3] = f2tf(w.w);
        }
        __syncthreads();

#pragma unroll
        for (int ks = 0; ks < 2; ks++) {
            const int kb = ks * 8;
            unsigned bfr[4][2];
#pragma unroll
            for (int nt = 0; nt < 4; nt++) {
                int col = wn + nt * 8 + gid;
                bfr[nt][0] = Bs[(kb + tig) * BS_STRIDE + col];
                bfr[nt][1] = Bs[(kb + tig + 4) * BS_STRIDE + col];
            }
#pragma unroll
            for (int mt = 0; mt < 4; mt++) {
                int row = wm + mt * 16 + gid;
                unsigned af[4];
                af[0] = As[row * AS_STRIDE + kb + tig];
                af[1] = As[(row + 8) * AS_STRIDE + kb + tig];
                af[2] = As[row * AS_STRIDE + kb + tig + 4];
                af[3] = As[(row + 8) * AS_STRIDE + kb + tig + 4];
#pragma unroll
                for (int nt = 0; nt < 4; nt++) mma_tf32(acc[mt][nt], af, bfr[nt]);
            }
        }
        __syncthreads();
    }

#pragma unroll
    for (int mt = 0; mt < 4; mt++) {
#pragma unroll
        for (int nt = 0; nt < 4; nt++) {
            int rr = row0 + wm + mt * 16 + gid;
            int cc = n0 + wn + nt * 8 + 2 * tig;
#pragma unroll
            for (int half = 0; half < 2; half++) {
                int row = rr + half * 8;
                float2 o2 = make_float2(acc[mt][nt][half * 2], acc[mt][nt][half * 2 + 1]);
                if (headMode) {
                    int b = row / rowsPerBatch;
                    int tr = row - b * rowsPerBatch;
                    int h = cc >> 6;
                    int d = cc & 63;
                    *(float2*)(C + ((((size_t)b * H_ + h) * rowsPerBatch + tr) << 6) + d) = o2;
                } else {
                    *(float2*)(C + (size_t)row * 1024 + cc) = o2;
                }
            }
        }
    }
}

__global__ __launch_bounds__(256) void k_proj_q(const float* __restrict__ A, const float* __restrict__ W)
{ gemm_tf32_body(A, W, g_q, T_, true); }
__global__ __launch_bounds__(256) void k_proj_k(const float* __restrict__ W)
{ gemm_tf32_body(g_values, W, g_k, L_, true); }
__global__ __launch_bounds__(256) void k_proj_v(const float* __restrict__ W)
{ gemm_tf32_body(g_values, W, g_v, L_, true); }
__global__ __launch_bounds__(256) void k_proj_r(const float* __restrict__ A, const float* __restrict__ W)
{ gemm_tf32_body(A, W, g_rk, R_, true); }
__global__ __launch_bounds__(256) void k_out(const float* __restrict__ W, float* __restrict__ out)
{ gemm_tf32_body(g_attn, W, out, 1, false); }

// ---------------- concat: values = [memory ; inputs] -------------------------------
__global__ __launch_bounds__(256) void k_concat(
    const float* __restrict__ mem, const float* __restrict__ inp)
{
    size_t i4 = (size_t)blockIdx.x * blockDim.x + threadIdx.x;
    size_t e = i4 * 4;
    int b = (int)(e >> 21);
    size_t rem = e & ((1u << 21) - 1);
    int l = (int)(rem >> 10);
    int d = (int)(rem & 1023);
    float4 val;
    if (l < M_) val = *(const float4*)(mem + ((size_t)b * M_ + l) * 1024 + d);
    else        val = *(const float4*)(inp + ((size_t)b * T_ + (l - M_)) * 1024 + d);
    *(float4*)(g_values + e) = val;
}

// ---------------- rel GEMM (tf32 mma), banded, written in shifted layout -----------
#define RS_STRIDE 72

__global__ __launch_bounds__(256) void k_relgemm(const float* __restrict__ rrb)
{
    const int r0 = blockIdx.x * 64;
    const int t0 = blockIdx.y * 64;
    if (r0 + 63 < T_ - t0 - 63 || r0 > T_ - t0 + L_ - 1) return;
    const int bh = blockIdx.z;
    const int h = bh & (H_ - 1);

    __shared__ unsigned Qs[64 * RS_STRIDE];
    __shared__ unsigned Rs[64 * RS_STRIDE];

    const int tid = threadIdx.x;
    const int lane = tid & 31, warp = tid >> 5;
    const int wm = (warp & 1) * 32, wn = (warp >> 1) * 16;
    const int gid = lane >> 2, tig = lane & 3;

#pragma unroll
    for (int u = 0; u < 4; u++) {
        int idx = tid + u * 256;
        int row = idx >> 4, dq = (idx & 15) << 2;
        float4 qv = *(const float4*)(g_q + (((size_t)bh * T_ + t0 + row) << 6) + dq);
        float4 bv = *(const float4*)(rrb + h * 64 + dq);
        unsigned* qd = &Qs[row * RS_STRIDE + dq];
        qd[0] = f2tf(qv.x + bv.x); qd[1] = f2tf(qv.y + bv.y);
        qd[2] = f2tf(qv.z + bv.z); qd[3] = f2tf(qv.w + bv.w);
        float4 rv = *(const float4*)(g_rk + (((size_t)h * R_ + r0 + row) << 6) + dq);
        unsigned* rd = &Rs[row * RS_STRIDE + dq];
        rd[0] = f2tf(rv.x); rd[1] = f2tf(rv.y);
        rd[2] = f2tf(rv.z); rd[3] = f2tf(rv.w);
    }
    __syncthreads();

    float acc[2][2][4];
#pragma unroll
    for (int mt = 0; mt < 2; mt++)
#pragma unroll
        for (int nt = 0; nt < 2; nt++)
#pragma unroll
            for (int c = 0; c < 4; c++) acc[mt][nt][c] = 0.f;

#pragma unroll
    for (int ks = 0; ks < 8; ks++) {
        const int kb = ks * 8;
        unsigned bfr[2][2];
#pragma unroll
        for (int nt = 0; nt < 2; nt++) {
            int col = wn + nt * 8 + gid;
            bfr[nt][0] = Rs[col * RS_STRIDE + kb + tig];
            bfr[nt][1] = Rs[col * RS_STRIDE + kb + tig + 4];
        }
#pragma unroll
        for (int mt = 0; mt < 2; mt++) {
            int row = wm + mt * 16 + gid;
            unsigned af[4];
            af[0] = Qs[row * RS_STRIDE + kb + tig];
            af[1] = Qs[(row + 8) * RS_STRIDE + kb + tig];
            af[2] = Qs[row * RS_STRIDE + kb + tig + 4];
            af[3] = Qs[(row + 8) * RS_STRIDE + kb + tig + 4];
#pragma unroll
            for (int nt = 0; nt < 2; nt++) mma_tf32(acc[mt][nt], af, bfr[nt]);
        }
    }

#pragma unroll
    for (int mt = 0; mt < 2; mt++) {
#pragma unroll
        for (int nt = 0; nt < 2; nt++) {
            int rbase = r0 + wn + nt * 8 + 2 * tig;
#pragma unroll
            for (int half = 0; half < 2; half++) {
                int t = t0 + wm + mt * 16 + gid + half * 8;
                size_t rowbase = ((size_t)bh * T_ + t) * (size_t)L_;
                int j0 = rbase - T_ + t;
                if (j0 >= 0 && j0 < L_) g_rel[rowbase + j0] = acc[mt][nt][half * 2];
                int j1 = j0 + 1;
                if (j1 >= 0 && j1 < L_) g_rel[rowbase + j1] = acc[mt][nt][half * 2 + 1];
            }
        }
    }
}

// ---------------- fused flash attention (tf32 mma) ---------------------------------
// 128 threads = 4 warps. Q-tile 64 rows, j-tile 64. Warp w owns rows [16w, 16w+16),
// all 64 cols: softmax rows never cross warps (reduce = shfl_xor over tig lanes).
#define FS 68                                   // smem stride (conflict-free)
#define FLASH_SMEM (4 * 64 * FS * 4)

__global__ __launch_bounds__(128) void k_flash(
    const float* __restrict__ mask, const float* __restrict__ rwb)
{
    extern __shared__ unsigned smu[];
    unsigned* Qs = smu;                 // [t][d]   A operand of S
    unsigned* Ks = smu + 64 * FS;       // [j][d]   B operand of S (col j, k d)
    unsigned* Vs = smu + 2 * 64 * FS;   // [d][j]   B operand of PV (col d, k j)
    unsigned* Ps = smu + 3 * 64 * FS;   // [t][j]   A operand of PV

    const int tid = threadIdx.x;
    const int lane = tid & 31, warp = tid >> 5;
    const int gid = lane >> 2, tig = lane & 3;
    const int wm = warp * 16;
    const int t0 = blockIdx.x * 64;
    const int h = blockIdx.y;
    const int b = blockIdx.z;
    const int bh = b * H_ + h;

    const int tA = t0 + wm + gid;
    const int tB = tA + 8;
    const float* relA = g_rel + ((size_t)bh * T_ + tA) * (size_t)L_;
    const float* relB = g_rel + ((size_t)bh * T_ + tB) * (size_t)L_;
    const float* mskA = mask + ((size_t)b * T_ + tA) * (size_t)L_;
    const float* mskB = mask + ((size_t)b * T_ + tB) * (size_t)L_;

    // Q tile + r_w_bias -> tf32 smem
#pragma unroll
    for (int u = 0; u < 8; u++) {
        int idx = tid + u * 128;
        int row = idx >> 4, dq = (idx & 15) << 2;
        float4 qv = *(const float4*)(g_q + (((size_t)bh * T_ + t0 + row) << 6) + dq);
        float4 bv = *(const float4*)(rwb + h * 64 + dq);
        unsigned* qd = &Qs[row * FS + dq];
        qd[0] = f2tf(qv.x + bv.x); qd[1] = f2tf(qv.y + bv.y);
        qd[2] = f2tf(qv.z + bv.z); qd[3] = f2tf(qv.w + bv.w);
    }

    float mA = -CUDART_INF_F, mB = -CUDART_INF_F, lA = 0.f, lB = 0.f;
    float o[8][4];
#pragma unroll
    for (int nt = 0; nt < 8; nt++)
#pragma unroll
        for (int c = 0; c < 4; c++) o[nt][c] = 0.f;

    for (int j0 = 0; j0 < L_; j0 += 64) {
        // stage K [j][d] and V^T [d][j]
#pragma unroll
        for (int u = 0; u < 8; u++) {
            int idx = tid + u * 128;
            int row = idx >> 4, dq = (idx & 15) << 2;
            float4 kv = *(const float4*)(g_k + (((size_t)bh * L_ + j0 + row) << 6) + dq);
            unsigned* kd = &Ks[row * FS + dq];
            kd[0] = f2tf(kv.x); kd[1] = f2tf(kv.y);
            kd[2] = f2tf(kv.z); kd[3] = f2tf(kv.w);
            float4 vv = *(const float4*)(g_v + (((size_t)bh * L_ + j0 + row) << 6) + dq);
            Vs[(dq + 0) * FS + row] = f2tf(vv.x);
            Vs[(dq + 1) * FS + row] = f2tf(vv.y);
            Vs[(dq + 2) * FS + row] = f2tf(vv.z);
            Vs[(dq + 3) * FS + row] = f2tf(vv.w);
        }
        __syncthreads();

        // S = Q K^T  (warp: 16 rows x 64 cols)
        float s[8][4];
#pragma unroll
        for (int nt = 0; nt < 8; nt++)
#pragma unroll
            for (int c = 0; c < 4; c++) s[nt][c] = 0.f;
#pragma unroll
        for (int ks = 0; ks < 8; ks++) {
            const int kb = ks * 8;
            unsigned af[4];
            af[0] = Qs[(wm + gid) * FS + kb + tig];
            af[1] = Qs[(wm + gid + 8) * FS + kb + tig];
            af[2] = Qs[(wm + gid) * FS + kb + tig + 4];
            af[3] = Qs[(wm + gid + 8) * FS + kb + tig + 4];
#pragma unroll
            for (int nt = 0; nt < 8; nt++) {
                unsigned bf[2];
                bf[0] = Ks[(nt * 8 + gid) * FS + kb + tig];
                bf[1] = Ks[(nt * 8 + gid) * FS + kb + tig + 4];
                mma_tf32(s[nt], af, bf);
            }
        }

        // + rel, * scale, mask
#pragma unroll
        for (int nt = 0; nt < 8; nt++) {
            int c = j0 + nt * 8 + 2 * tig;
            float2 ra = *(const float2*)(relA + c);
            float2 rb = *(const float2*)(relB + c);
            float2 ma = *(const float2*)(mskA + c);
            float2 mb = *(const float2*)(mskB + c);
            s[nt][0] = (s[nt][0] + ra.x) * 0.125f - (1.f - ma.x) * 1e30f;
            s[nt][1] = (s[nt][1] + ra.y) * 0.125f - (1.f - ma.y) * 1e30f;
            s[nt][2] = (s[nt][2] + rb.x) * 0.125f - (1.f - mb.x) * 1e30f;
            s[nt][3] = (s[nt][3] + rb.y) * 0.125f - (1.f - mb.y) * 1e30f;
        }

        // online softmax (rows A=gid, B=gid+8 within warp; reduce over tig lanes)
        float mxA = -CUDART_INF_F, mxB = -CUDART_INF_F;
#pragma unroll
        for (int nt = 0; nt < 8; nt++) {
            mxA = fmaxf(mxA, fmaxf(s[nt][0], s[nt][1]));
            mxB = fmaxf(mxB, fmaxf(s[nt][2], s[nt][3]));
        }
        mxA = fmaxf(mxA, __shfl_xor_sync(0xffffffffu, mxA, 1));
        mxA = fmaxf(mxA, __shfl_xor_sync(0xffffffffu, mxA, 2));
        mxB = fmaxf(mxB, __shfl_xor_sync(0xffffffffu, mxB, 1));
        mxB = fmaxf(mxB, __shfl_xor_sync(0xffffffffu, mxB, 2));

        float mnA = fmaxf(mA, mxA), mnB = fmaxf(mB, mxB);
        float aA = __expf(mA - mnA), aB = __expf(mB - mnB);
        float rsA = 0.f, rsB = 0.f;
#pragma unroll
        for (int nt = 0; nt < 8; nt++) {
            // round P to tf32 so l matches the weights PV actually uses
            float p0 = __uint_as_float(f2tf(__expf(s[nt][0] - mnA)));
            float p1 = __uint_as_float(f2tf(__expf(s[nt][1] - mnA)));
            float p2 = __uint_as_float(f2tf(__expf(s[nt][2] - mnB)));
            float p3 = __uint_as_float(f2tf(__expf(s[nt][3] - mnB)));
            s[nt][0] = p0; s[nt][1] = p1; s[nt][2] = p2; s[nt][3] = p3;
            rsA += p0 + p1; rsB += p2 + p3;
        }
        rsA += __shfl_xor_sync(0xffffffffu, rsA, 1);
        rsA += __shfl_xor_sync(0xffffffffu, rsA, 2);
        rsB += __shfl_xor_sync(0xffffffffu, rsB, 1);
        rsB += __shfl_xor_sync(0xffffffffu, rsB, 2);
        mA = mnA; mB = mnB;
        lA = lA * aA + rsA; lB = lB * aB + rsB;
#pragma unroll
        for (int nt = 0; nt < 8; nt++) {
            o[nt][0] *= aA; o[nt][1] *= aA;
            o[nt][2] *= aB; o[nt][3] *= aB;
        }

        // P -> smem (A-operand layout)
#pragma unroll
        for (int nt = 0; nt < 8; nt++) {
            int cc = nt * 8 + 2 * tig;
            Ps[(wm + gid) * FS + cc]     = __float_as_uint(s[nt][0]);
            Ps[(wm + gid) * FS + cc + 1] = __float_as_uint(s[nt][1]);
            Ps[(wm + gid + 8) * FS + cc]     = __float_as_uint(s[nt][2]);
            Ps[(wm + gid + 8) * FS + cc + 1] = __float_as_uint(s[nt][3]);
        }
        __syncthreads();

        // O += P V
#pragma unroll
        for (int ks = 0; ks < 8; ks++) {
            const int kb = ks * 8;
            unsigned af[4];
            af[0] = Ps[(wm + gid) * FS + kb + tig];
            af[1] = Ps[(wm + gid + 8) * FS + kb + tig];
            af[2] = Ps[(wm + gid) * FS + kb + tig + 4];
            af[3] = Ps[(wm + gid + 8) * FS + kb + tig + 4];
#pragma unroll
            for (int nt = 0; nt < 8; nt++) {
                unsigned bf[2];
                bf[0] = Vs[(nt * 8 + gid) * FS + kb + tig];
                bf[1] = Vs[(nt * 8 + gid) * FS + kb + tig + 4];
                mma_tf32(o[nt], af, bf);
            }
        }
        __syncthreads();   // protect Ks/Vs/Ps before next stage
    }

    // normalize + write attn [B*T, H*64]
    float invA = 1.f / lA, invB = 1.f / lB;
#pragma unroll
    for (int nt = 0; nt < 8; nt++) {
        int col = h * 64 + nt * 8 + 2 * tig;
        *(float2*)(g_attn + (((size_t)b * T_ + tA) << 10) + col) =
            make_float2(o[nt][0] * invA, o[nt][1] * invA);
        *(float2*)(g_attn + (((size_t)b * T_ + tB) << 10) + col) =
            make_float2(o[nt][2] * invB, o[nt][3] * invB);
    }
}

// ---------------- launch ------------------------------------------------------------
extern "C" void kernel_launch(void* const* d_in, const int* in_sizes, int n_in,
                              void* d_out, int out_size)
{
    (void)in_sizes; (void)n_in; (void)out_size;
    const float* inputs = (const float*)d_in[0];
    const float* mask   = (const float*)d_in[1];
    const float* pos    = (const float*)d_in[2];
    const float* mem    = (const float*)d_in[3];
    const float* Wq     = (const float*)d_in[4];
    const float* Wk     = (const float*)d_in[5];
    const float* Wv     = (const float*)d_in[6];
    const float* Wr     = (const float*)d_in[7];
    const float* rwb    = (const float*)d_in[8];
    const float* rrb    = (const float*)d_in[9];
    const float* Wout   = (const float*)d_in[10];
    float* out = (float*)d_out;

    cudaFuncSetAttribute(k_flash, cudaFuncAttributeMaxDynamicSharedMemorySize, FLASH_SMEM);

    k_concat<<<(B_ * L_ * D_ / 4) / 256, 256>>>(mem, inputs);

    k_proj_q<<<dim3(8, (B_ * T_) / 128), 256>>>(inputs, Wq);
    k_proj_k<<<dim3(8, (B_ * L_) / 128), 256>>>(Wk);
    k_proj_v<<<dim3(8, (B_ * L_) / 128), 256>>>(Wv);
    k_proj_r<<<dim3(8, R_ / 128), 256>>>(pos, Wr);

    k_relgemm<<<dim3(R_ / 64, T_ / 64, B_ * H_), 256>>>(rrb);

    k_flash<<<dim3(T_ / 64, H_, B_), 128, FLASH_SMEM>>>(mask, rwb);

    k_out<<<dim3(8, (B_ * T_) / 128), 256>>>(Wout, out);
}

// round 10
// speedup vs baseline: 2.5786x; 1.2299x over previous
#include <cuda_runtime.h>
#include <math_constants.h>

#define B_ 2
#define T_ 1024
#define M_ 1024
#define D_ 1024
#define H_ 16
#define L_ 2048
#define R_ 3072

// ---------------- scratch (allocation-free rule: __device__ globals) ----------------
__device__ float g_q[B_ * H_ * T_ * 64];        // [B*H, T, 64]
__device__ float g_k[B_ * H_ * L_ * 64];        // [B*H, L, 64]
__device__ float g_v[B_ * H_ * L_ * 64];        // [B*H, L, 64]
__device__ float g_rk[H_ * R_ * 64];            // [H, R, 64]
__device__ float g_rel[B_ * H_ * T_ * L_];      // shifted rel [B*H, T, L]
__device__ float g_attn[B_ * T_ * H_ * 64];     // [B*T, H*64]

// ---------------- tf32 mma helpers -------------------------------------------------
__device__ __forceinline__ unsigned f2tf(float f) {
    unsigned u;
    asm("cvt.rna.tf32.f32 %0, %1;" : "=r"(u) : "f"(f));
    return u;
}

__device__ __forceinline__ void mma_tf32(float* c, const unsigned* a, const unsigned* b) {
    asm volatile(
        "mma.sync.aligned.m16n8k8.row.col.f32.tf32.tf32.f32 "
        "{%0,%1,%2,%3}, {%4,%5,%6,%7}, {%8,%9}, {%0,%1,%2,%3};"
        : "+f"(c[0]), "+f"(c[1]), "+f"(c[2]), "+f"(c[3])
        : "r"(a[0]), "r"(a[1]), "r"(a[2]), "r"(a[3]), "r"(b[0]), "r"(b[1]));
}

__device__ __forceinline__ void cp16(unsigned dst, const void* src) {
    asm volatile("cp.async.cg.shared.global [%0], [%1], 16;" :: "r"(dst), "l"(src));
}
#define CP_COMMIT() asm volatile("cp.async.commit_group;")
#define CP_WAIT1() asm volatile("cp.async.wait_group 1;")
#define CP_WAIT0() asm volatile("cp.async.wait_group 0;")

// ---------------- tf32 GEMM, cp.async double-buffered ------------------------------
// BM=128, BN=128, BK=16. 256 threads = 8 warps 2(M)x4(N); warp tile 64x32.
#define AS_STRIDE 20
#define BS_STRIDE 136

__device__ __forceinline__ void gemm_tf32_body(
    const float* __restrict__ Atile,     // points at row0 of A
    const float* __restrict__ W,
    float* __restrict__ C, int row0, int rowsPerBatch, bool headMode)
{
    __shared__ float As[2][128 * AS_STRIDE];
    __shared__ float Bs[2][16 * BS_STRIDE];

    const int tid = threadIdx.x;
    const int lane = tid & 31, warp = tid >> 5;
    const int wm = (warp & 1) * 64, wn = (warp >> 1) * 32;
    const int gid = lane >> 2, tig = lane & 3;
    const int n0 = blockIdx.x * 128;

    // staging coordinates (fixed per thread)
    const int ar0 = tid >> 2, akq = (tid & 3) << 2;   // A: 2x (row, 4 k)
    const int ar1 = ar0 + 64;
    const int bk0 = tid >> 5, bc = (tid & 31) << 2;   // B: 2x (k row, 4 cols)
    const int bk1 = bk0 + 8;

    unsigned sA0[2], sA1[2], sB0[2], sB1[2];
    {
        unsigned a_base = (unsigned)__cvta_generic_to_shared(&As[0][0]);
        unsigned b_base = (unsigned)__cvta_generic_to_shared(&Bs[0][0]);
#pragma unroll
        for (int s = 0; s < 2; s++) {
            sA0[s] = a_base + (unsigned)(s * 128 * AS_STRIDE + ar0 * AS_STRIDE + akq) * 4u;
            sA1[s] = a_base + (unsigned)(s * 128 * AS_STRIDE + ar1 * AS_STRIDE + akq) * 4u;
            sB0[s] = b_base + (unsigned)(s * 16 * BS_STRIDE + bk0 * BS_STRIDE + bc) * 4u;
            sB1[s] = b_base + (unsigned)(s * 16 * BS_STRIDE + bk1 * BS_STRIDE + bc) * 4u;
        }
    }

    float acc[4][4][4];
#pragma unroll
    for (int mt = 0; mt < 4; mt++)
#pragma unroll
        for (int nt = 0; nt < 4; nt++)
#pragma unroll
            for (int c = 0; c < 4; c++) acc[mt][nt][c] = 0.f;

    // prologue: stage tile 0 into buffer 0
    cp16(sA0[0], Atile + (size_t)ar0 * 1024 + akq);
    cp16(sA1[0], Atile + (size_t)ar1 * 1024 + akq);
    cp16(sB0[0], W + (size_t)bk0 * 1024 + n0 + bc);
    cp16(sB1[0], W + (size_t)bk1 * 1024 + n0 + bc);
    CP_COMMIT();

    for (int it = 0; it < 64; it++) {
        const int cur = it & 1;
        if (it + 1 < 64) {
            const int k0 = (it + 1) * 16;
            const int nxt = cur ^ 1;
            cp16(sA0[nxt], Atile + (size_t)ar0 * 1024 + k0 + akq);
            cp16(sA1[nxt], Atile + (size_t)ar1 * 1024 + k0 + akq);
            cp16(sB0[nxt], W + (size_t)(k0 + bk0) * 1024 + n0 + bc);
            cp16(sB1[nxt], W + (size_t)(k0 + bk1) * 1024 + n0 + bc);
            CP_COMMIT();
            CP_WAIT1();
        } else {
            CP_WAIT0();
        }
        __syncthreads();

        const float* A_s = As[cur];
        const float* B_s = Bs[cur];
#pragma unroll
        for (int ks = 0; ks < 2; ks++) {
            const int kb = ks * 8;
            unsigned bfr[4][2];
#pragma unroll
            for (int nt = 0; nt < 4; nt++) {
                int col = wn + nt * 8 + gid;
                bfr[nt][0] = f2tf(B_s[(kb + tig) * BS_STRIDE + col]);
                bfr[nt][1] = f2tf(B_s[(kb + tig + 4) * BS_STRIDE + col]);
            }
#pragma unroll
            for (int mt = 0; mt < 4; mt++) {
                int row = wm + mt * 16 + gid;
                unsigned af[4];
                af[0] = f2tf(A_s[row * AS_STRIDE + kb + tig]);
                af[1] = f2tf(A_s[(row + 8) * AS_STRIDE + kb + tig]);
                af[2] = f2tf(A_s[row * AS_STRIDE + kb + tig + 4]);
                af[3] = f2tf(A_s[(row + 8) * AS_STRIDE + kb + tig + 4]);
#pragma unroll
                for (int nt = 0; nt < 4; nt++) mma_tf32(acc[mt][nt], af, bfr[nt]);
            }
        }
        __syncthreads();
    }

#pragma unroll
    for (int mt = 0; mt < 4; mt++) {
#pragma unroll
        for (int nt = 0; nt < 4; nt++) {
            int rr = row0 + wm + mt * 16 + gid;
            int cc = n0 + wn + nt * 8 + 2 * tig;
#pragma unroll
            for (int half = 0; half < 2; half++) {
                int row = rr + half * 8;
                float2 o2 = make_float2(acc[mt][nt][half * 2], acc[mt][nt][half * 2 + 1]);
                if (headMode) {
                    int b = row / rowsPerBatch;
                    int tr = row - b * rowsPerBatch;
                    int h = cc >> 6;
                    int d = cc & 63;
                    *(float2*)(C + ((((size_t)b * H_ + h) * rowsPerBatch + tr) << 6) + d) = o2;
                } else {
                    *(float2*)(C + (size_t)row * 1024 + cc) = o2;
                }
            }
        }
    }
}

__global__ __launch_bounds__(256, 2) void k_proj_q(
    const float* __restrict__ A, const float* __restrict__ W)
{
    int row0 = blockIdx.y * 128;
    gemm_tf32_body(A + (size_t)row0 * 1024, W, g_q, row0, T_, true);
}

// K/V projections read [memory ; inputs] without materializing the concat:
// 128-row tiles never straddle the 1024 boundary -> per-block source select.
// NOTE: output global (g_k / g_v) must be referenced from DEVICE code, never
// passed as a host-side kernel argument.
__device__ __forceinline__ const float* kv_src(
    const float* mem, const float* inp, int row0)
{
    int b = row0 >> 11;
    int l0 = row0 & (L_ - 1);
    return (l0 < M_)
        ? mem + ((size_t)b * M_ + l0) * 1024
        : inp + ((size_t)b * T_ + (l0 - M_)) * 1024;
}

__global__ __launch_bounds__(256, 2) void k_proj_k(
    const float* __restrict__ mem, const float* __restrict__ inp,
    const float* __restrict__ W)
{
    int row0 = blockIdx.y * 128;
    gemm_tf32_body(kv_src(mem, inp, row0), W, g_k, row0, L_, true);
}

__global__ __launch_bounds__(256, 2) void k_proj_v(
    const float* __restrict__ mem, const float* __restrict__ inp,
    const float* __restrict__ W)
{
    int row0 = blockIdx.y * 128;
    gemm_tf32_body(kv_src(mem, inp, row0), W, g_v, row0, L_, true);
}

__global__ __launch_bounds__(256, 2) void k_proj_r(
    const float* __restrict__ A, const float* __restrict__ W)
{
    int row0 = blockIdx.y * 128;
    gemm_tf32_body(A + (size_t)row0 * 1024, W, g_rk, row0, R_, true);
}
__global__ __launch_bounds__(256, 2) void k_out(
    const float* __restrict__ W, float* __restrict__ out)
{
    int row0 = blockIdx.y * 128;
    gemm_tf32_body(g_attn + (size_t)row0 * 1024, W, out, row0, 1, false);
}

// ---------------- rel GEMM (tf32 mma), banded, written in shifted layout -----------
#define RS_STRIDE 72

__global__ __launch_bounds__(256) void k_relgemm(const float* __restrict__ rrb)
{
    const int r0 = blockIdx.x * 64;
    const int t0 = blockIdx.y * 64;
    if (r0 + 63 < T_ - t0 - 63 || r0 > T_ - t0 + L_ - 1) return;
    const int bh = blockIdx.z;
    const int h = bh & (H_ - 1);

    __shared__ unsigned Qs[64 * RS_STRIDE];
    __shared__ unsigned Rs[64 * RS_STRIDE];

    const int tid = threadIdx.x;
    const int lane = tid & 31, warp = tid >> 5;
    const int wm = (warp & 1) * 32, wn = (warp >> 1) * 16;
    const int gid = lane >> 2, tig = lane & 3;

#pragma unroll
    for (int u = 0; u < 4; u++) {
        int idx = tid + u * 256;
        int row = idx >> 4, dq = (idx & 15) << 2;
        float4 qv = *(const float4*)(g_q + (((size_t)bh * T_ + t0 + row) << 6) + dq);
        float4 bv = *(const float4*)(rrb + h * 64 + dq);
        unsigned* qd = &Qs[row * RS_STRIDE + dq];
        qd[0] = f2tf(qv.x + bv.x); qd[1] = f2tf(qv.y + bv.y);
        qd[2] = f2tf(qv.z + bv.z); qd[3] = f2tf(qv.w + bv.w);
        float4 rv = *(const float4*)(g_rk + (((size_t)h * R_ + r0 + row) << 6) + dq);
        unsigned* rd = &Rs[row * RS_STRIDE + dq];
        rd[0] = f2tf(rv.x); rd[1] = f2tf(rv.y);
        rd[2] = f2tf(rv.z); rd[3] = f2tf(rv.w);
    }
    __syncthreads();

    float acc[2][2][4];
#pragma unroll
    for (int mt = 0; mt < 2; mt++)
#pragma unroll
        for (int nt = 0; nt < 2; nt++)
#pragma unroll
            for (int c = 0; c < 4; c++) acc[mt][nt][c] = 0.f;

#pragma unroll
    for (int ks = 0; ks < 8; ks++) {
        const int kb = ks * 8;
        unsigned bfr[2][2];
#pragma unroll
        for (int nt = 0; nt < 2; nt++) {
            int col = wn + nt * 8 + gid;
            bfr[nt][0] = Rs[col * RS_STRIDE + kb + tig];
            bfr[nt][1] = Rs[col * RS_STRIDE + kb + tig + 4];
        }
#pragma unroll
        for (int mt = 0; mt < 2; mt++) {
            int row = wm + mt * 16 + gid;
            unsigned af[4];
            af[0] = Qs[row * RS_STRIDE + kb + tig];
            af[1] = Qs[(row + 8) * RS_STRIDE + kb + tig];
            af[2] = Qs[row * RS_STRIDE + kb + tig + 4];
            af[3] = Qs[(row + 8) * RS_STRIDE + kb + tig + 4];
#pragma unroll
            for (int nt = 0; nt < 2; nt++) mma_tf32(acc[mt][nt], af, bfr[nt]);
        }
    }

#pragma unroll
    for (int mt = 0; mt < 2; mt++) {
#pragma unroll
        for (int nt = 0; nt < 2; nt++) {
            int rbase = r0 + wn + nt * 8 + 2 * tig;
#pragma unroll
            for (int half = 0; half < 2; half++) {
                int t = t0 + wm + mt * 16 + gid + half * 8;
                size_t rowbase = ((size_t)bh * T_ + t) * (size_t)L_;
                int j0 = rbase - T_ + t;
                if (j0 >= 0 && j0 < L_) g_rel[rowbase + j0] = acc[mt][nt][half * 2];
                int j1 = j0 + 1;
                if (j1 >= 0 && j1 < L_) g_rel[rowbase + j1] = acc[mt][nt][half * 2 + 1];
            }
        }
    }
}

// ---------------- fused flash attention (tf32 mma) ---------------------------------
// 256 threads = 8 warps. Q-tile 128 rows, j-tile 64. Warp w owns rows [16w, 16w+16),
// all 64 cols; softmax rows never cross warps.
#define FS 68
#define FLASH_SMEM ((128 * FS + 64 * FS + 64 * FS + 128 * FS) * 4)

__global__ __launch_bounds__(256, 2) void k_flash(
    const float* __restrict__ mask, const float* __restrict__ rwb)
{
    extern __shared__ unsigned smu[];
    unsigned* Qs = smu;                       // [t 128][d]  A of S
    unsigned* Ks = smu + 128 * FS;            // [j 64][d]   B of S
    unsigned* Vs = smu + (128 + 64) * FS;     // [j 64][d]   B of PV
    unsigned* Ps = smu + (128 + 128) * FS;    // [t 128][j]  A of PV

    const int tid = threadIdx.x;
    const int lane = tid & 31, warp = tid >> 5;
    const int gid = lane >> 2, tig = lane & 3;
    const int wm = warp * 16;
    const int t0 = blockIdx.x * 128;
    const int h = blockIdx.y;
    const int b = blockIdx.z;
    const int bh = b * H_ + h;

    const int tA = t0 + wm + gid;
    const int tB = tA + 8;
    const float* relA = g_rel + ((size_t)bh * T_ + tA) * (size_t)L_;
    const float* relB = g_rel + ((size_t)bh * T_ + tB) * (size_t)L_;
    const float* mskA = mask + ((size_t)b * T_ + tA) * (size_t)L_;
    const float* mskB = mask + ((size_t)b * T_ + tB) * (size_t)L_;

    // Q tile (128 x 64) + r_w_bias -> tf32 smem
#pragma unroll
    for (int u = 0; u < 8; u++) {
        int idx = tid + u * 256;
        int row = idx >> 4, dq = (idx & 15) << 2;
        float4 qv = *(const float4*)(g_q + (((size_t)bh * T_ + t0 + row) << 6) + dq);
        float4 bv = *(const float4*)(rwb + h * 64 + dq);
        unsigned* qd = &Qs[row * FS + dq];
        qd[0] = f2tf(qv.x + bv.x); qd[1] = f2tf(qv.y + bv.y);
        qd[2] = f2tf(qv.z + bv.z); qd[3] = f2tf(qv.w + bv.w);
    }

    float mA = -CUDART_INF_F, mB = -CUDART_INF_F, lA = 0.f, lB = 0.f;
    float o[8][4];
#pragma unroll
    for (int nt = 0; nt < 8; nt++)
#pragma unroll
        for (int c = 0; c < 4; c++) o[nt][c] = 0.f;

    for (int j0 = 0; j0 < L_; j0 += 64) {
        // stage K and V, both [j][d] (64 x 64 each)
#pragma unroll
        for (int u = 0; u < 4; u++) {
            int idx = tid + u * 256;
            int row = idx >> 4, dq = (idx & 15) << 2;
            float4 kv = *(const float4*)(g_k + (((size_t)bh * L_ + j0 + row) << 6) + dq);
            unsigned* kd = &Ks[row * FS + dq];
            kd[0] = f2tf(kv.x); kd[1] = f2tf(kv.y);
            kd[2] = f2tf(kv.z); kd[3] = f2tf(kv.w);
            float4 vv = *(const float4*)(g_v + (((size_t)bh * L_ + j0 + row) << 6) + dq);
            unsigned* vd = &Vs[row * FS + dq];
            vd[0] = f2tf(vv.x); vd[1] = f2tf(vv.y);
            vd[2] = f2tf(vv.z); vd[3] = f2tf(vv.w);
        }
        __syncthreads();

        // S = Q K^T  (warp: 16 rows x 64 cols)
        float s[8][4];
#pragma unroll
        for (int nt = 0; nt < 8; nt++)
#pragma unroll
            for (int c = 0; c < 4; c++) s[nt][c] = 0.f;
#pragma unroll
        for (int ks = 0; ks < 8; ks++) {
            const int kb = ks * 8;
            unsigned af[4];
            af[0] = Qs[(wm + gid) * FS + kb + tig];
            af[1] = Qs[(wm + gid + 8) * FS + kb + tig];
            af[2] = Qs[(wm + gid) * FS + kb + tig + 4];
            af[3] = Qs[(wm + gid + 8) * FS + kb + tig + 4];
#pragma unroll
            for (int nt = 0; nt < 8; nt++) {
                unsigned bf[2];
                bf[0] = Ks[(nt * 8 + gid) * FS + kb + tig];
                bf[1] = Ks[(nt * 8 + gid) * FS + kb + tig + 4];
                mma_tf32(s[nt], af, bf);
            }
        }

        // + rel, * scale, mask
#pragma unroll
        for (int nt = 0; nt < 8; nt++) {
            int c = j0 + nt * 8 + 2 * tig;
            float2 ra = *(const float2*)(relA + c);
            float2 rb = *(const float2*)(relB + c);
            float2 ma = *(const float2*)(mskA + c);
            float2 mb = *(const float2*)(mskB + c);
            s[nt][0] = (s[nt][0] + ra.x) * 0.125f - (1.f - ma.x) * 1e30f;
            s[nt][1] = (s[nt][1] + ra.y) * 0.125f - (1.f - ma.y) * 1e30f;
            s[nt][2] = (s[nt][2] + rb.x) * 0.125f - (1.f - mb.x) * 1e30f;
            s[nt][3] = (s[nt][3] + rb.y) * 0.125f - (1.f - mb.y) * 1e30f;
        }

        // online softmax (rows A=gid, B=gid+8; reduce over the 4 tig lanes)
        float mxA = -CUDART_INF_F, mxB = -CUDART_INF_F;
#pragma unroll
        for (int nt = 0; nt < 8; nt++) {
            mxA = fmaxf(mxA, fmaxf(s[nt][0], s[nt][1]));
            mxB = fmaxf(mxB, fmaxf(s[nt][2], s[nt][3]));
        }
        mxA = fmaxf(mxA, __shfl_xor_sync(0xffffffffu, mxA, 1));
        mxA = fmaxf(mxA, __shfl_xor_sync(0xffffffffu, mxA, 2));
        mxB = fmaxf(mxB, __shfl_xor_sync(0xffffffffu, mxB, 1));
        mxB = fmaxf(mxB, __shfl_xor_sync(0xffffffffu, mxB, 2));

        float mnA = fmaxf(mA, mxA), mnB = fmaxf(mB, mxB);
        float aA = __expf(mA - mnA), aB = __expf(mB - mnB);
        float rsA = 0.f, rsB = 0.f;
#pragma unroll
        for (int nt = 0; nt < 8; nt++) {
            // round P to tf32 so l matches the weights PV actually uses
            float p0 = __uint_as_float(f2tf(__expf(s[nt][0] - mnA)));
            float p1 = __uint_as_float(f2tf(__expf(s[nt][1] - mnA)));
            float p2 = __uint_as_float(f2tf(__expf(s[nt][2] - mnB)));
            float p3 = __uint_as_float(f2tf(__expf(s[nt][3] - mnB)));
            s[nt][0] = p0; s[nt][1] = p1; s[nt][2] = p2; s[nt][3] = p3;
            rsA += p0 + p1; rsB += p2 + p3;
        }
        rsA += __shfl_xor_sync(0xffffffffu, rsA, 1);
        rsA += __shfl_xor_sync(0xffffffffu, rsA, 2);
        rsB += __shfl_xor_sync(0xffffffffu, rsB, 1);
        rsB += __shfl_xor_sync(0xffffffffu, rsB, 2);
        mA = mnA; mB = mnB;
        lA = lA * aA + rsA; lB = lB * aB + rsB;
#pragma unroll
        for (int nt = 0; nt < 8; nt++) {
            o[nt][0] *= aA; o[nt][1] *= aA;
            o[nt][2] *= aB; o[nt][3] *= aB;
        }

        // P -> smem (A-operand layout)
#pragma unroll
        for (int nt = 0; nt < 8; nt++) {
            int cc = nt * 8 + 2 * tig;
            Ps[(wm + gid) * FS + cc]     = __float_as_uint(s[nt][0]);
            Ps[(wm + gid) * FS + cc + 1] = __float_as_uint(s[nt][1]);
            Ps[(wm + gid + 8) * FS + cc]     = __float_as_uint(s[nt][2]);
            Ps[(wm + gid + 8) * FS + cc + 1] = __float_as_uint(s[nt][3]);
        }
        __syncthreads();

        // O += P V   (B fragment from Vs[j][d])
#pragma unroll
        for (int ks = 0; ks < 8; ks++) {
            const int kb = ks * 8;
            unsigned af[4];
            af[0] = Ps[(wm + gid) * FS + kb + tig];
            af[1] = Ps[(wm + gid + 8) * FS + kb + tig];
            af[2] = Ps[(wm + gid) * FS + kb + tig + 4];
            af[3] = Ps[(wm + gid + 8) * FS + kb + tig + 4];
#pragma unroll
            for (int nt = 0; nt < 8; nt++) {
                unsigned bf[2];
                bf[0] = Vs[(kb + tig) * FS + nt * 8 + gid];
                bf[1] = Vs[(kb + tig + 4) * FS + nt * 8 + gid];
                mma_tf32(o[nt], af, bf);
            }
        }
        __syncthreads();   // protect Ks/Vs/Ps before next stage
    }

    // normalize + write attn [B*T, H*64]
    float invA = 1.f / lA, invB = 1.f / lB;
#pragma unroll
    for (int nt = 0; nt < 8; nt++) {
        int col = h * 64 + nt * 8 + 2 * tig;
        *(float2*)(g_attn + (((size_t)b * T_ + tA) << 10) + col) =
            make_float2(o[nt][0] * invA, o[nt][1] * invA);
        *(float2*)(g_attn + (((size_t)b * T_ + tB) << 10) + col) =
            make_float2(o[nt][2] * invB, o[nt][3] * invB);
    }
}

// ---------------- launch ------------------------------------------------------------
extern "C" void kernel_launch(void* const* d_in, const int* in_sizes, int n_in,
                              void* d_out, int out_size)
{
    (void)in_sizes; (void)n_in; (void)out_size;
    const float* inputs = (const float*)d_in[0];
    const float* mask   = (const float*)d_in[1];
    const float* pos    = (const float*)d_in[2];
    const float* mem    = (const float*)d_in[3];
    const float* Wq     = (const float*)d_in[4];
    const float* Wk     = (const float*)d_in[5];
    const float* Wv     = (const float*)d_in[6];
    const float* Wr     = (const float*)d_in[7];
    const float* rwb    = (const float*)d_in[8];
    const float* rrb    = (const float*)d_in[9];
    const float* Wout   = (const float*)d_in[10];
    float* out = (float*)d_out;

    cudaFuncSetAttribute(k_flash, cudaFuncAttributeMaxDynamicSharedMemorySize, FLASH_SMEM);

    k_proj_q<<<dim3(8, (B_ * T_) / 128), 256>>>(inputs, Wq);
    k_proj_k<<<dim3(8, (B_ * L_) / 128), 256>>>(mem, inputs, Wk);
    k_proj_v<<<dim3(8, (B_ * L_) / 128), 256>>>(mem, inputs, Wv);
    k_proj_r<<<dim3(8, R_ / 128), 256>>>(pos, Wr);

    k_relgemm<<<dim3(R_ / 64, T_ / 64, B_ * H_), 256>>>(rrb);

    k_flash<<<dim3(T_ / 128, H_, B_), 256, FLASH_SMEM>>>(mask, rwb);

    k_out<<<dim3(8, (B_ * T_) / 128), 256>>>(Wout, out);
}

// round 11
// speedup vs baseline: 2.5973x; 1.0073x over previous
#include <cuda_runtime.h>
#include <math_constants.h>

#define B_ 2
#define T_ 1024
#define M_ 1024
#define D_ 1024
#define H_ 16
#define L_ 2048
#define R_ 3072

// ---------------- scratch (allocation-free rule: __device__ globals) ----------------
__device__ float g_q[B_ * H_ * T_ * 64];        // [B*H, T, 64]
__device__ float g_k[B_ * H_ * L_ * 64];        // [B*H, L, 64]
__device__ float g_v[B_ * H_ * L_ * 64];        // [B*H, L, 64]
__device__ float g_rk[H_ * R_ * 64];            // [H, R, 64]
__device__ float g_rel[B_ * H_ * T_ * L_];      // shifted rel [B*H, T, L]
__device__ float g_attn[B_ * T_ * H_ * 64];     // [B*T, H*64]

// ---------------- tf32 mma helpers -------------------------------------------------
__device__ __forceinline__ unsigned f2tf(float f) {
    unsigned u;
    asm("cvt.rna.tf32.f32 %0, %1;" : "=r"(u) : "f"(f));
    return u;
}

__device__ __forceinline__ void mma_tf32(float* c, const unsigned* a, const unsigned* b) {
    asm volatile(
        "mma.sync.aligned.m16n8k8.row.col.f32.tf32.tf32.f32 "
        "{%0,%1,%2,%3}, {%4,%5,%6,%7}, {%8,%9}, {%0,%1,%2,%3};"
        : "+f"(c[0]), "+f"(c[1]), "+f"(c[2]), "+f"(c[3])
        : "r"(a[0]), "r"(a[1]), "r"(a[2]), "r"(a[3]), "r"(b[0]), "r"(b[1]));
}

__device__ __forceinline__ void cp16(unsigned dst, const void* src) {
    asm volatile("cp.async.cg.shared.global [%0], [%1], 16;" :: "r"(dst), "l"(src));
}
#define CP_COMMIT() asm volatile("cp.async.commit_group;")
#define CP_WAIT1() asm volatile("cp.async.wait_group 1;")
#define CP_WAIT0() asm volatile("cp.async.wait_group 0;")

__device__ __forceinline__ void cvt4_inplace(unsigned* p) {
    uint4 v = *(uint4*)p;
    v.x = f2tf(__uint_as_float(v.x));
    v.y = f2tf(__uint_as_float(v.y));
    v.z = f2tf(__uint_as_float(v.z));
    v.w = f2tf(__uint_as_float(v.w));
    *(uint4*)p = v;
}

// ---------------- tf32 GEMM, BK=32, cp.async double-buffered, convert-in-place -----
// BM=128, BN=128, BK=32. 256 threads = 8 warps 2(M)x4(N); warp tile 64x32.
#define AS2 36
#define BS2 136
#define A_WORDS (128 * AS2)      // 4608
#define B_WORDS (32 * BS2)       // 4352
#define GEMM_SMEM ((2 * A_WORDS + 2 * B_WORDS) * 4)   // 71680 B

__device__ __forceinline__ void gemm_tf32_body(
    const float* __restrict__ Atile,     // points at row0 of A
    const float* __restrict__ W,
    float* __restrict__ C, int row0, int rowsPerBatch, bool headMode)
{
    extern __shared__ unsigned sm[];
    unsigned* Abuf = sm;                  // [2][A_WORDS]
    unsigned* Bbuf = sm + 2 * A_WORDS;    // [2][B_WORDS]

    const int tid = threadIdx.x;
    const int lane = tid & 31, warp = tid >> 5;
    const int wm = (warp & 1) * 64, wn = (warp >> 1) * 32;
    const int gid = lane >> 2, tig = lane & 3;
    const int n0 = blockIdx.x * 128;

    // staging chunk coordinates (4 A chunks + 4 B chunks per thread)
    unsigned aOff[4], bOff[4];
    const float* aG[4];
    const float* bG[4];
#pragma unroll
    for (int u = 0; u < 4; u++) {
        int idx = tid + u * 256;
        int r = idx >> 3, kq = (idx & 7) << 2;       // A: 128 rows x 32 k
        aOff[u] = (unsigned)(r * AS2 + kq);
        aG[u] = Atile + (size_t)r * 1024 + kq;
        int kk = idx >> 5, c4 = (idx & 31) << 2;     // B: 32 k x 128 cols
        bOff[u] = (unsigned)(kk * BS2 + c4);
        bG[u] = W + (size_t)kk * 1024 + n0 + c4;
    }
    const unsigned a_base = (unsigned)__cvta_generic_to_shared(Abuf);
    const unsigned b_base = (unsigned)__cvta_generic_to_shared(Bbuf);

    float acc[4][4][4];
#pragma unroll
    for (int mt = 0; mt < 4; mt++)
#pragma unroll
        for (int nt = 0; nt < 4; nt++)
#pragma unroll
            for (int c = 0; c < 4; c++) acc[mt][nt][c] = 0.f;

    // prologue: stage tile 0 into buffer 0
#pragma unroll
    for (int u = 0; u < 4; u++) {
        cp16(a_base + aOff[u] * 4u, aG[u]);
        cp16(b_base + bOff[u] * 4u, bG[u]);
    }
    CP_COMMIT();

    for (int it = 0; it < 32; it++) {
        const int cur = it & 1;
        if (it + 1 < 32) {
            const int k0 = (it + 1) * 32;
            const unsigned an = a_base + (unsigned)((cur ^ 1) * A_WORDS) * 4u;
            const unsigned bn = b_base + (unsigned)((cur ^ 1) * B_WORDS) * 4u;
#pragma unroll
            for (int u = 0; u < 4; u++) {
                cp16(an + aOff[u] * 4u, aG[u] + k0);
                cp16(bn + bOff[u] * 4u, bG[u] + (size_t)k0 * 1024);
            }
            CP_COMMIT();
            CP_WAIT1();
        } else {
            CP_WAIT0();
        }

        // convert own staged words in place (no barrier needed: own cp.async group)
        unsigned* Ac = Abuf + cur * A_WORDS;
        unsigned* Bc = Bbuf + cur * B_WORDS;
#pragma unroll
        for (int u = 0; u < 4; u++) {
            cvt4_inplace(&Ac[aOff[u]]);
            cvt4_inplace(&Bc[bOff[u]]);
        }
        __syncthreads();   // all conversions visible before mma

#pragma unroll
        for (int ks = 0; ks < 4; ks++) {
            const int kb = ks * 8;
            unsigned bfr[4][2];
#pragma unroll
            for (int nt = 0; nt < 4; nt++) {
                int col = wn + nt * 8 + gid;
                bfr[nt][0] = Bc[(kb + tig) * BS2 + col];
                bfr[nt][1] = Bc[(kb + tig + 4) * BS2 + col];
            }
#pragma unroll
            for (int mt = 0; mt < 4; mt++) {
                int row = wm + mt * 16 + gid;
                unsigned af[4];
                af[0] = Ac[row * AS2 + kb + tig];
                af[1] = Ac[(row + 8) * AS2 + kb + tig];
                af[2] = Ac[row * AS2 + kb + tig + 4];
                af[3] = Ac[(row + 8) * AS2 + kb + tig + 4];
#pragma unroll
                for (int nt = 0; nt < 4; nt++) mma_tf32(acc[mt][nt], af, bfr[nt]);
            }
        }
        __syncthreads();   // all reads done before next prefetch overwrites cur
    }

#pragma unroll
    for (int mt = 0; mt < 4; mt++) {
#pragma unroll
        for (int nt = 0; nt < 4; nt++) {
            int rr = row0 + wm + mt * 16 + gid;
            int cc = n0 + wn + nt * 8 + 2 * tig;
#pragma unroll
            for (int half = 0; half < 2; half++) {
                int row = rr + half * 8;
                float2 o2 = make_float2(acc[mt][nt][half * 2], acc[mt][nt][half * 2 + 1]);
                if (headMode) {
                    int b = row / rowsPerBatch;
                    int tr = row - b * rowsPerBatch;
                    int h = cc >> 6;
                    int d = cc & 63;
                    *(float2*)(C + ((((size_t)b * H_ + h) * rowsPerBatch + tr) << 6) + d) = o2;
                } else {
                    *(float2*)(C + (size_t)row * 1024 + cc) = o2;
                }
            }
        }
    }
}

__global__ __launch_bounds__(256, 2) void k_proj_q(
    const float* __restrict__ A, const float* __restrict__ W)
{
    int row0 = blockIdx.y * 128;
    gemm_tf32_body(A + (size_t)row0 * 1024, W, g_q, row0, T_, true);
}

// K/V projections read [memory ; inputs] without materializing the concat:
// 128-row tiles never straddle the 1024 boundary -> per-block source select.
// Output global referenced from DEVICE code only.
__device__ __forceinline__ const float* kv_src(
    const float* mem, const float* inp, int row0)
{
    int b = row0 >> 11;
    int l0 = row0 & (L_ - 1);
    return (l0 < M_)
        ? mem + ((size_t)b * M_ + l0) * 1024
        : inp + ((size_t)b * T_ + (l0 - M_)) * 1024;
}

__global__ __launch_bounds__(256, 2) void k_proj_k(
    const float* __restrict__ mem, const float* __restrict__ inp,
    const float* __restrict__ W)
{
    int row0 = blockIdx.y * 128;
    gemm_tf32_body(kv_src(mem, inp, row0), W, g_k, row0, L_, true);
}

__global__ __launch_bounds__(256, 2) void k_proj_v(
    const float* __restrict__ mem, const float* __restrict__ inp,
    const float* __restrict__ W)
{
    int row0 = blockIdx.y * 128;
    gemm_tf32_body(kv_src(mem, inp, row0), W, g_v, row0, L_, true);
}

__global__ __launch_bounds__(256, 2) void k_proj_r(
    const float* __restrict__ A, const float* __restrict__ W)
{
    int row0 = blockIdx.y * 128;
    gemm_tf32_body(A + (size_t)row0 * 1024, W, g_rk, row0, R_, true);
}
__global__ __launch_bounds__(256, 2) void k_out(
    const float* __restrict__ W, float* __restrict__ out)
{
    int row0 = blockIdx.y * 128;
    gemm_tf32_body(g_attn + (size_t)row0 * 1024, W, out, row0, 1, false);
}

// ---------------- rel GEMM: 128x128 tiles, banded, shifted-layout store ------------
// rel[b,h,t,r] = (q[b,t,h,:]+rrb[h,:]) . rk[r,h,:];  shifted[t,j] = rel[t, T - t + j]
#define RS2 68
#define REL_SMEM (2 * 128 * RS2 * 4)   // 69632 B

__global__ __launch_bounds__(256, 2) void k_relgemm(const float* __restrict__ rrb)
{
    const int r0 = blockIdx.x * 128;
    const int t0 = blockIdx.y * 128;
    if (r0 + 127 < T_ - t0 - 127 || r0 > T_ - t0 + L_ - 1) return;
    const int bh = blockIdx.z;
    const int h = bh & (H_ - 1);

    extern __shared__ unsigned sm[];
    unsigned* Qs = sm;                 // [t 128][d 64] stride RS2
    unsigned* Rs = sm + 128 * RS2;     // [r 128][d 64] stride RS2

    const int tid = threadIdx.x;
    const int lane = tid & 31, warp = tid >> 5;
    const int wm = (warp & 1) * 64, wn = (warp >> 1) * 32;
    const int gid = lane >> 2, tig = lane & 3;

    const unsigned q_base = (unsigned)__cvta_generic_to_shared(Qs);
    const unsigned r_base = (unsigned)__cvta_generic_to_shared(Rs);

    // stage Q (128x64) and R (128x64), 8 chunks each via cp.async
    unsigned off[8];
    int dqs[8];
#pragma unroll
    for (int u = 0; u < 8; u++) {
        int idx = tid + u * 256;
        int row = idx >> 4, dq = (idx & 15) << 2;
        off[u] = (unsigned)(row * RS2 + dq);
        dqs[u] = dq;
        cp16(q_base + off[u] * 4u, g_q + (((size_t)bh * T_ + t0 + row) << 6) + dq);
        cp16(r_base + off[u] * 4u, g_rk + (((size_t)h * R_ + r0 + row) << 6) + dq);
    }
    CP_COMMIT();
    CP_WAIT0();

    // convert own words: Q gets +rrb bias, R plain
#pragma unroll
    for (int u = 0; u < 8; u++) {
        float4 bv = *(const float4*)(rrb + h * 64 + dqs[u]);
        unsigned* qp = &Qs[off[u]];
        uint4 qv = *(uint4*)qp;
        qv.x = f2tf(__uint_as_float(qv.x) + bv.x);
        qv.y = f2tf(__uint_as_float(qv.y) + bv.y);
        qv.z = f2tf(__uint_as_float(qv.z) + bv.z);
        qv.w = f2tf(__uint_as_float(qv.w) + bv.w);
        *(uint4*)qp = qv;
        cvt4_inplace(&Rs[off[u]]);
    }
    __syncthreads();

    float acc[4][4][4];
#pragma unroll
    for (int mt = 0; mt < 4; mt++)
#pragma unroll
        for (int nt = 0; nt < 4; nt++)
#pragma unroll
            for (int c = 0; c < 4; c++) acc[mt][nt][c] = 0.f;

#pragma unroll
    for (int ks = 0; ks < 8; ks++) {
        const int kb = ks * 8;
        unsigned bfr[4][2];
#pragma unroll
        for (int nt = 0; nt < 4; nt++) {
            int col = wn + nt * 8 + gid;
            bfr[nt][0] = Rs[col * RS2 + kb + tig];
            bfr[nt][1] = Rs[col * RS2 + kb + tig + 4];
        }
#pragma unroll
        for (int mt = 0; mt < 4; mt++) {
            int row = wm + mt * 16 + gid;
            unsigned af[4];
            af[0] = Qs[row * RS2 + kb + tig];
            af[1] = Qs[(row + 8) * RS2 + kb + tig];
            af[2] = Qs[row * RS2 + kb + tig + 4];
            af[3] = Qs[(row + 8) * RS2 + kb + tig + 4];
#pragma unroll
            for (int nt = 0; nt < 4; nt++) mma_tf32(acc[mt][nt], af, bfr[nt]);
        }
    }

    // epilogue: shifted column j = r - T + t, bounds-checked
#pragma unroll
    for (int mt = 0; mt < 4; mt++) {
#pragma unroll
        for (int nt = 0; nt < 4; nt++) {
            int rbase = r0 + wn + nt * 8 + 2 * tig;
#pragma unroll
            for (int half = 0; half < 2; half++) {
                int t = t0 + wm + mt * 16 + gid + half * 8;
                size_t rowbase = ((size_t)bh * T_ + t) * (size_t)L_;
                int j0 = rbase - T_ + t;
                if (j0 >= 0 && j0 < L_) g_rel[rowbase + j0] = acc[mt][nt][half * 2];
                int j1 = j0 + 1;
                if (j1 >= 0 && j1 < L_) g_rel[rowbase + j1] = acc[mt][nt][half * 2 + 1];
            }
        }
    }
}

// ---------------- fused flash attention (tf32 mma) ---------------------------------
// 256 threads = 8 warps. Q-tile 128 rows, j-tile 64. Warp w owns rows [16w, 16w+16),
// all 64 cols; softmax rows never cross warps.
#define FS 68
#define FLASH_SMEM ((128 * FS + 64 * FS + 64 * FS + 128 * FS) * 4)

__global__ __launch_bounds__(256, 2) void k_flash(
    const float* __restrict__ mask, const float* __restrict__ rwb)
{
    extern __shared__ unsigned smu[];
    unsigned* Qs = smu;                       // [t 128][d]  A of S
    unsigned* Ks = smu + 128 * FS;            // [j 64][d]   B of S
    unsigned* Vs = smu + (128 + 64) * FS;     // [j 64][d]   B of PV
    unsigned* Ps = smu + (128 + 128) * FS;    // [t 128][j]  A of PV

    const int tid = threadIdx.x;
    const int lane = tid & 31, warp = tid >> 5;
    const int gid = lane >> 2, tig = lane & 3;
    const int wm = warp * 16;
    const int t0 = blockIdx.x * 128;
    const int h = blockIdx.y;
    const int b = blockIdx.z;
    const int bh = b * H_ + h;

    const int tA = t0 + wm + gid;
    const int tB = tA + 8;
    const float* relA = g_rel + ((size_t)bh * T_ + tA) * (size_t)L_;
    const float* relB = g_rel + ((size_t)bh * T_ + tB) * (size_t)L_;
    const float* mskA = mask + ((size_t)b * T_ + tA) * (size_t)L_;
    const float* mskB = mask + ((size_t)b * T_ + tB) * (size_t)L_;

    // Q tile (128 x 64) + r_w_bias -> tf32 smem
#pragma unroll
    for (int u = 0; u < 8; u++) {
        int idx = tid + u * 256;
        int row = idx >> 4, dq = (idx & 15) << 2;
        float4 qv = *(const float4*)(g_q + (((size_t)bh * T_ + t0 + row) << 6) + dq);
        float4 bv = *(const float4*)(rwb + h * 64 + dq);
        unsigned* qd = &Qs[row * FS + dq];
        qd[0] = f2tf(qv.x + bv.x); qd[1] = f2tf(qv.y + bv.y);
        qd[2] = f2tf(qv.z + bv.z); qd[3] = f2tf(qv.w + bv.w);
    }

    float mA = -CUDART_INF_F, mB = -CUDART_INF_F, lA = 0.f, lB = 0.f;
    float o[8][4];
#pragma unroll
    for (int nt = 0; nt < 8; nt++)
#pragma unroll
        for (int c = 0; c < 4; c++) o[nt][c] = 0.f;

    for (int j0 = 0; j0 < L_; j0 += 64) {
        // stage K and V, both [j][d] (64 x 64 each)
#pragma unroll
        for (int u = 0; u < 4; u++) {
            int idx = tid + u * 256;
            int row = idx >> 4, dq = (idx & 15) << 2;
            float4 kv = *(const float4*)(g_k + (((size_t)bh * L_ + j0 + row) << 6) + dq);
            unsigned* kd = &Ks[row * FS + dq];
            kd[0] = f2tf(kv.x); kd[1] = f2tf(kv.y);
            kd[2] = f2tf(kv.z); kd[3] = f2tf(kv.w);
            float4 vv = *(const float4*)(g_v + (((size_t)bh * L_ + j0 + row) << 6) + dq);
            unsigned* vd = &Vs[row * FS + dq];
            vd[0] = f2tf(vv.x); vd[1] = f2tf(vv.y);
            vd[2] = f2tf(vv.z); vd[3] = f2tf(vv.w);
        }
        __syncthreads();

        // S = Q K^T  (warp: 16 rows x 64 cols)
        float s[8][4];
#pragma unroll
        for (int nt = 0; nt < 8; nt++)
#pragma unroll
            for (int c = 0; c < 4; c++) s[nt][c] = 0.f;
#pragma unroll
        for (int ks = 0; ks < 8; ks++) {
            const int kb = ks * 8;
            unsigned af[4];
            af[0] = Qs[(wm + gid) * FS + kb + tig];
            af[1] = Qs[(wm + gid + 8) * FS + kb + tig];
            af[2] = Qs[(wm + gid) * FS + kb + tig + 4];
            af[3] = Qs[(wm + gid + 8) * FS + kb + tig + 4];
#pragma unroll
            for (int nt = 0; nt < 8; nt++) {
                unsigned bf[2];
                bf[0] = Ks[(nt * 8 + gid) * FS + kb + tig];
                bf[1] = Ks[(nt * 8 + gid) * FS + kb + tig + 4];
                mma_tf32(s[nt], af, bf);
            }
        }

        // + rel, * scale, mask
#pragma unroll
        for (int nt = 0; nt < 8; nt++) {
            int c = j0 + nt * 8 + 2 * tig;
            float2 ra = *(const float2*)(relA + c);
            float2 rb = *(const float2*)(relB + c);
            float2 ma = *(const float2*)(mskA + c);
            float2 mb = *(const float2*)(mskB + c);
            s[nt][0] = (s[nt][0] + ra.x) * 0.125f - (1.f - ma.x) * 1e30f;
            s[nt][1] = (s[nt][1] + ra.y) * 0.125f - (1.f - ma.y) * 1e30f;
            s[nt][2] = (s[nt][2] + rb.x) * 0.125f - (1.f - mb.x) * 1e30f;
            s[nt][3] = (s[nt][3] + rb.y) * 0.125f - (1.f - mb.y) * 1e30f;
        }

        // online softmax (rows A=gid, B=gid+8; reduce over the 4 tig lanes)
        float mxA = -CUDART_INF_F, mxB = -CUDART_INF_F;
#pragma unroll
        for (int nt = 0; nt < 8; nt++) {
            mxA = fmaxf(mxA, fmaxf(s[nt][0], s[nt][1]));
            mxB = fmaxf(mxB, fmaxf(s[nt][2], s[nt][3]));
        }
        mxA = fmaxf(mxA, __shfl_xor_sync(0xffffffffu, mxA, 1));
        mxA = fmaxf(mxA, __shfl_xor_sync(0xffffffffu, mxA, 2));
        mxB = fmaxf(mxB, __shfl_xor_sync(0xffffffffu, mxB, 1));
        mxB = fmaxf(mxB, __shfl_xor_sync(0xffffffffu, mxB, 2));

        float mnA = fmaxf(mA, mxA), mnB = fmaxf(mB, mxB);
        float aA = __expf(mA - mnA), aB = __expf(mB - mnB);
        float rsA = 0.f, rsB = 0.f;
#pragma unroll
        for (int nt = 0; nt < 8; nt++) {
            // round P to tf32 so l matches the weights PV actually uses
            float p0 = __uint_as_float(f2tf(__expf(s[nt][0] - mnA)));
            float p1 = __uint_as_float(f2tf(__expf(s[nt][1] - mnA)));
            float p2 = __uint_as_float(f2tf(__expf(s[nt][2] - mnB)));
            float p3 = __uint_as_float(f2tf(__expf(s[nt][3] - mnB)));
            s[nt][0] = p0; s[nt][1] = p1; s[nt][2] = p2; s[nt][3] = p3;
            rsA += p0 + p1; rsB += p2 + p3;
        }
        rsA += __shfl_xor_sync(0xffffffffu, rsA, 1);
        rsA += __shfl_xor_sync(0xffffffffu, rsA, 2);
        rsB += __shfl_xor_sync(0xffffffffu, rsB, 1);
        rsB += __shfl_xor_sync(0xffffffffu, rsB, 2);
        mA = mnA; mB = mnB;
        lA = lA * aA + rsA; lB = lB * aB + rsB;
#pragma unroll
        for (int nt = 0; nt < 8; nt++) {
            o[nt][0] *= aA; o[nt][1] *= aA;
            o[nt][2] *= aB; o[nt][3] *= aB;
        }

        // P -> smem (A-operand layout); warp reads only rows it wrote -> warpsync
#pragma unroll
        for (int nt = 0; nt < 8; nt++) {
            int cc = nt * 8 + 2 * tig;
            Ps[(wm + gid) * FS + cc]     = __float_as_uint(s[nt][0]);
            Ps[(wm + gid) * FS + cc + 1] = __float_as_uint(s[nt][1]);
            Ps[(wm + gid + 8) * FS + cc]     = __float_as_uint(s[nt][2]);
            Ps[(wm + gid + 8) * FS + cc + 1] = __float_as_uint(s[nt][3]);
        }
        __syncwarp();

        // O += P V   (B fragment from Vs[j][d])
#pragma unroll
        for (int ks = 0; ks < 8; ks++) {
            const int kb = ks * 8;
            unsigned af[4];
            af[0] = Ps[(wm + gid) * FS + kb + tig];
            af[1] = Ps[(wm + gid + 8) * FS + kb + tig];
            af[2] = Ps[(wm + gid) * FS + kb + tig + 4];
            af[3] = Ps[(wm + gid + 8) * FS + kb + tig + 4];
#pragma unroll
            for (int nt = 0; nt < 8; nt++) {
                unsigned bf[2];
                bf[0] = Vs[(kb + tig) * FS + nt * 8 + gid];
                bf[1] = Vs[(kb + tig + 4) * FS + nt * 8 + gid];
                mma_tf32(o[nt], af, bf);
            }
        }
        __syncthreads();   // protect Ks/Vs before next stage
    }

    // normalize + write attn [B*T, H*64]
    float invA = 1.f / lA, invB = 1.f / lB;
#pragma unroll
    for (int nt = 0; nt < 8; nt++) {
        int col = h * 64 + nt * 8 + 2 * tig;
        *(float2*)(g_attn + (((size_t)b * T_ + tA) << 10) + col) =
            make_float2(o[nt][0] * invA, o[nt][1] * invA);
        *(float2*)(g_attn + (((size_t)b * T_ + tB) << 10) + col) =
            make_float2(o[nt][2] * invB, o[nt][3] * invB);
    }
}

// ---------------- launch ------------------------------------------------------------
extern "C" void kernel_launch(void* const* d_in, const int* in_sizes, int n_in,
                              void* d_out, int out_size)
{
    (void)in_sizes; (void)n_in; (void)out_size;
    const float* inputs = (const float*)d_in[0];
    const float* mask   = (const float*)d_in[1];
    const float* pos    = (const float*)d_in[2];
    const float* mem    = (const float*)d_in[3];
    const float* Wq     = (const float*)d_in[4];
    const float* Wk     = (const float*)d_in[5];
    const float* Wv     = (const float*)d_in[6];
    const float* Wr     = (const float*)d_in[7];
    const float* rwb    = (const float*)d_in[8];
    const float* rrb    = (const float*)d_in[9];
    const float* Wout   = (const float*)d_in[10];
    float* out = (float*)d_out;

    cudaFuncSetAttribute(k_proj_q, cudaFuncAttributeMaxDynamicSharedMemorySize, GEMM_SMEM);
    cudaFuncSetAttribute(k_proj_k, cudaFuncAttributeMaxDynamicSharedMemorySize, GEMM_SMEM);
    cudaFuncSetAttribute(k_proj_v, cudaFuncAttributeMaxDynamicSharedMemorySize, GEMM_SMEM);
    cudaFuncSetAttribute(k_proj_r, cudaFuncAttributeMaxDynamicSharedMemorySize, GEMM_SMEM);
    cudaFuncSetAttribute(k_out,    cudaFuncAttributeMaxDynamicSharedMemorySize, GEMM_SMEM);
    cudaFuncSetAttribute(k_relgemm, cudaFuncAttributeMaxDynamicSharedMemorySize, REL_SMEM);
    cudaFuncSetAttribute(k_flash,  cudaFuncAttributeMaxDynamicSharedMemorySize, FLASH_SMEM);

    k_proj_q<<<dim3(8, (B_ * T_) / 128), 256, GEMM_SMEM>>>(inputs, Wq);
    k_proj_k<<<dim3(8, (B_ * L_) / 128), 256, GEMM_SMEM>>>(mem, inputs, Wk);
    k_proj_v<<<dim3(8, (B_ * L_) / 128), 256, GEMM_SMEM>>>(mem, inputs, Wv);
    k_proj_r<<<dim3(8, R_ / 128), 256, GEMM_SMEM>>>(pos, Wr);

    k_relgemm<<<dim3(R_ / 128, T_ / 128, B_ * H_), 256, REL_SMEM>>>(rrb);

    k_flash<<<dim3(T_ / 128, H_, B_), 256, FLASH_SMEM>>>(mask, rwb);

    k_out<<<dim3(8, (B_ * T_) / 128), 256, GEMM_SMEM>>>(Wout, out);
}

// round 12
// speedup vs baseline: 2.8210x; 1.0861x over previous
#include <cuda_runtime.h>
#include <math_constants.h>

#define B_ 2
#define T_ 1024
#define M_ 1024
#define D_ 1024
#define H_ 16
#define L_ 2048
#define R_ 3072

// ---------------- scratch (allocation-free rule: __device__ globals) ----------------
__device__ float g_q[B_ * H_ * T_ * 64];        // [B*H, T, 64]
__device__ float g_k[B_ * H_ * L_ * 64];        // [B*H, L, 64]
__device__ float g_v[B_ * H_ * L_ * 64];        // [B*H, L, 64]
__device__ float g_rk[H_ * R_ * 64];            // [H, R, 64]
__device__ float g_rel[B_ * H_ * T_ * L_];      // shifted rel [B*H, T, L]
__device__ float g_attn[B_ * T_ * H_ * 64];     // [B*T, H*64]

// ---------------- tf32 mma helpers -------------------------------------------------
__device__ __forceinline__ unsigned f2tf(float f) {
    unsigned u;
    asm("cvt.rna.tf32.f32 %0, %1;" : "=r"(u) : "f"(f));
    return u;
}

__device__ __forceinline__ void mma_tf32(float* c, const unsigned* a, const unsigned* b) {
    asm volatile(
        "mma.sync.aligned.m16n8k8.row.col.f32.tf32.tf32.f32 "
        "{%0,%1,%2,%3}, {%4,%5,%6,%7}, {%8,%9}, {%0,%1,%2,%3};"
        : "+f"(c[0]), "+f"(c[1]), "+f"(c[2]), "+f"(c[3])
        : "r"(a[0]), "r"(a[1]), "r"(a[2]), "r"(a[3]), "r"(b[0]), "r"(b[1]));
}

__device__ __forceinline__ void cp16(unsigned dst, const void* src) {
    asm volatile("cp.async.cg.shared.global [%0], [%1], 16;" :: "r"(dst), "l"(src));
}
#define CP_COMMIT() asm volatile("cp.async.commit_group;")
#define CP_WAIT1() asm volatile("cp.async.wait_group 1;")
#define CP_WAIT0() asm volatile("cp.async.wait_group 0;")

__device__ __forceinline__ void cvt4_inplace(unsigned* p) {
    uint4 v = *(uint4*)p;
    v.x = f2tf(__uint_as_float(v.x));
    v.y = f2tf(__uint_as_float(v.y));
    v.z = f2tf(__uint_as_float(v.z));
    v.w = f2tf(__uint_as_float(v.w));
    *(uint4*)p = v;
}

// ---------------- tf32 GEMM, BK=32, cp.async double-buffered, convert-in-place -----
// BM=128, BN=128, BK=32. 256 threads = 8 warps 2(M)x4(N); warp tile 64x32.
#define AS2 36
#define BS2 136
#define A_WORDS (128 * AS2)      // 4608
#define B_WORDS (32 * BS2)       // 4352
#define GEMM_SMEM ((2 * A_WORDS + 2 * B_WORDS) * 4)   // 71680 B

__device__ __forceinline__ void gemm_tf32_body(
    const float* __restrict__ Atile,     // points at row0 of A
    const float* __restrict__ W,
    float* __restrict__ C, int row0, int n0, int rowsPerBatch, bool headMode)
{
    extern __shared__ unsigned sm[];
    unsigned* Abuf = sm;                  // [2][A_WORDS]
    unsigned* Bbuf = sm + 2 * A_WORDS;    // [2][B_WORDS]

    const int tid = threadIdx.x;
    const int lane = tid & 31, warp = tid >> 5;
    const int wm = (warp & 1) * 64, wn = (warp >> 1) * 32;
    const int gid = lane >> 2, tig = lane & 3;

    // staging chunk coordinates (4 A chunks + 4 B chunks per thread)
    unsigned aOff[4], bOff[4];
    const float* aG[4];
    const float* bG[4];
#pragma unroll
    for (int u = 0; u < 4; u++) {
        int idx = tid + u * 256;
        int r = idx >> 3, kq = (idx & 7) << 2;       // A: 128 rows x 32 k
        aOff[u] = (unsigned)(r * AS2 + kq);
        aG[u] = Atile + (size_t)r * 1024 + kq;
        int kk = idx >> 5, c4 = (idx & 31) << 2;     // B: 32 k x 128 cols
        bOff[u] = (unsigned)(kk * BS2 + c4);
        bG[u] = W + (size_t)kk * 1024 + n0 + c4;
    }
    const unsigned a_base = (unsigned)__cvta_generic_to_shared(Abuf);
    const unsigned b_base = (unsigned)__cvta_generic_to_shared(Bbuf);

    float acc[4][4][4];
#pragma unroll
    for (int mt = 0; mt < 4; mt++)
#pragma unroll
        for (int nt = 0; nt < 4; nt++)
#pragma unroll
            for (int c = 0; c < 4; c++) acc[mt][nt][c] = 0.f;

    // prologue: stage tile 0 into buffer 0
#pragma unroll
    for (int u = 0; u < 4; u++) {
        cp16(a_base + aOff[u] * 4u, aG[u]);
        cp16(b_base + bOff[u] * 4u, bG[u]);
    }
    CP_COMMIT();

    for (int it = 0; it < 32; it++) {
        const int cur = it & 1;
        if (it + 1 < 32) {
            const int k0 = (it + 1) * 32;
            const unsigned an = a_base + (unsigned)((cur ^ 1) * A_WORDS) * 4u;
            const unsigned bn = b_base + (unsigned)((cur ^ 1) * B_WORDS) * 4u;
#pragma unroll
            for (int u = 0; u < 4; u++) {
                cp16(an + aOff[u] * 4u, aG[u] + k0);
                cp16(bn + bOff[u] * 4u, bG[u] + (size_t)k0 * 1024);
            }
            CP_COMMIT();
            CP_WAIT1();
        } else {
            CP_WAIT0();
        }

        // convert own staged words in place (no barrier needed: own cp.async group)
        unsigned* Ac = Abuf + cur * A_WORDS;
        unsigned* Bc = Bbuf + cur * B_WORDS;
#pragma unroll
        for (int u = 0; u < 4; u++) {
            cvt4_inplace(&Ac[aOff[u]]);
            cvt4_inplace(&Bc[bOff[u]]);
        }
        __syncthreads();   // all conversions visible before mma

#pragma unroll
        for (int ks = 0; ks < 4; ks++) {
            const int kb = ks * 8;
            unsigned bfr[4][2];
#pragma unroll
            for (int nt = 0; nt < 4; nt++) {
                int col = wn + nt * 8 + gid;
                bfr[nt][0] = Bc[(kb + tig) * BS2 + col];
                bfr[nt][1] = Bc[(kb + tig + 4) * BS2 + col];
            }
#pragma unroll
            for (int mt = 0; mt < 4; mt++) {
                int row = wm + mt * 16 + gid;
                unsigned af[4];
                af[0] = Ac[row * AS2 + kb + tig];
                af[1] = Ac[(row + 8) * AS2 + kb + tig];
                af[2] = Ac[row * AS2 + kb + tig + 4];
                af[3] = Ac[(row + 8) * AS2 + kb + tig + 4];
#pragma unroll
                for (int nt = 0; nt < 4; nt++) mma_tf32(acc[mt][nt], af, bfr[nt]);
            }
        }
        __syncthreads();   // all reads done before next prefetch overwrites cur
    }

#pragma unroll
    for (int mt = 0; mt < 4; mt++) {
#pragma unroll
        for (int nt = 0; nt < 4; nt++) {
            int rr = row0 + wm + mt * 16 + gid;
            int cc = n0 + wn + nt * 8 + 2 * tig;
#pragma unroll
            for (int half = 0; half < 2; half++) {
                int row = rr + half * 8;
                float2 o2 = make_float2(acc[mt][nt][half * 2], acc[mt][nt][half * 2 + 1]);
                if (headMode) {
                    int b = row / rowsPerBatch;
                    int tr = row - b * rowsPerBatch;
                    int h = cc >> 6;
                    int d = cc & 63;
                    *(float2*)(C + ((((size_t)b * H_ + h) * rowsPerBatch + tr) << 6) + d) = o2;
                } else {
                    *(float2*)(C + (size_t)row * 1024 + cc) = o2;
                }
            }
        }
    }
}

// K/V source select: [memory ; inputs], 128-row tiles never straddle the boundary.
__device__ __forceinline__ const float* kv_src(
    const float* mem, const float* inp, int row0)
{
    int b = row0 >> 11;
    int l0 = row0 & (L_ - 1);
    return (l0 < M_)
        ? mem + ((size_t)b * M_ + l0) * 1024
        : inp + ((size_t)b * T_ + (l0 - M_)) * 1024;
}

// ---------------- merged projection launch: Q | K | V | R --------------------------
// grid.x = 832 blocks: [0,128) Q, [128,384) K, [384,640) V, [640,832) R.
// One launch -> 2 CTAs/SM occupancy across the whole projection phase.
__global__ __launch_bounds__(256, 2) void k_proj_all(
    const float* __restrict__ inputs, const float* __restrict__ mem,
    const float* __restrict__ pos,
    const float* __restrict__ Wq, const float* __restrict__ Wk,
    const float* __restrict__ Wv, const float* __restrict__ Wr)
{
    const int bx = blockIdx.x;
    if (bx < 128) {
        int local = bx;
        int row0 = (local >> 3) * 128, n0 = (local & 7) * 128;
        gemm_tf32_body(inputs + (size_t)row0 * 1024, Wq, g_q, row0, n0, T_, true);
    } else if (bx < 384) {
        int local = bx - 128;
        int row0 = (local >> 3) * 128, n0 = (local & 7) * 128;
        gemm_tf32_body(kv_src(mem, inputs, row0), Wk, g_k, row0, n0, L_, true);
    } else if (bx < 640) {
        int local = bx - 384;
        int row0 = (local >> 3) * 128, n0 = (local & 7) * 128;
        gemm_tf32_body(kv_src(mem, inputs, row0), Wv, g_v, row0, n0, L_, true);
    } else {
        int local = bx - 640;
        int row0 = (local >> 3) * 128, n0 = (local & 7) * 128;
        gemm_tf32_body(pos + (size_t)row0 * 1024, Wr, g_rk, row0, n0, R_, true);
    }
}

__global__ __launch_bounds__(256, 2) void k_out(
    const float* __restrict__ W, float* __restrict__ out)
{
    int row0 = blockIdx.y * 128;
    gemm_tf32_body(g_attn + (size_t)row0 * 1024, W, out, row0, blockIdx.x * 128, 1, false);
}

// ---------------- rel GEMM: 128x128 tiles, banded, shifted-layout store ------------
// rel[b,h,t,r] = (q[b,t,h,:]+rrb[h,:]) . rk[r,h,:];  shifted[t,j] = rel[t, T - t + j]
#define RS2 68
#define REL_SMEM (2 * 128 * RS2 * 4)   // 69632 B

__global__ __launch_bounds__(256, 2) void k_relgemm(const float* __restrict__ rrb)
{
    const int r0 = blockIdx.x * 128;
    const int t0 = blockIdx.y * 128;
    if (r0 + 127 < T_ - t0 - 127 || r0 > T_ - t0 + L_ - 1) return;
    const int bh = blockIdx.z;
    const int h = bh & (H_ - 1);

    extern __shared__ unsigned sm[];
    unsigned* Qs = sm;                 // [t 128][d 64] stride RS2
    unsigned* Rs = sm + 128 * RS2;     // [r 128][d 64] stride RS2

    const int tid = threadIdx.x;
    const int lane = tid & 31, warp = tid >> 5;
    const int wm = (warp & 1) * 64, wn = (warp >> 1) * 32;
    const int gid = lane >> 2, tig = lane & 3;

    const unsigned q_base = (unsigned)__cvta_generic_to_shared(Qs);
    const unsigned r_base = (unsigned)__cvta_generic_to_shared(Rs);

    // stage Q (128x64) and R (128x64), 8 chunks each via cp.async
    unsigned off[8];
    int dqs[8];
#pragma unroll
    for (int u = 0; u < 8; u++) {
        int idx = tid + u * 256;
        int row = idx >> 4, dq = (idx & 15) << 2;
        off[u] = (unsigned)(row * RS2 + dq);
        dqs[u] = dq;
        cp16(q_base + off[u] * 4u, g_q + (((size_t)bh * T_ + t0 + row) << 6) + dq);
        cp16(r_base + off[u] * 4u, g_rk + (((size_t)h * R_ + r0 + row) << 6) + dq);
    }
    CP_COMMIT();
    CP_WAIT0();

    // convert own words: Q gets +rrb bias, R plain
#pragma unroll
    for (int u = 0; u < 8; u++) {
        float4 bv = *(const float4*)(rrb + h * 64 + dqs[u]);
        unsigned* qp = &Qs[off[u]];
        uint4 qv = *(uint4*)qp;
        qv.x = f2tf(__uint_as_float(qv.x) + bv.x);
        qv.y = f2tf(__uint_as_float(qv.y) + bv.y);
        qv.z = f2tf(__uint_as_float(qv.z) + bv.z);
        qv.w = f2tf(__uint_as_float(qv.w) + bv.w);
        *(uint4*)qp = qv;
        cvt4_inplace(&Rs[off[u]]);
    }
    __syncthreads();

    float acc[4][4][4];
#pragma unroll
    for (int mt = 0; mt < 4; mt++)
#pragma unroll
        for (int nt = 0; nt < 4; nt++)
#pragma unroll
            for (int c = 0; c < 4; c++) acc[mt][nt][c] = 0.f;

#pragma unroll
    for (int ks = 0; ks < 8; ks++) {
        const int kb = ks * 8;
        unsigned bfr[4][2];
#pragma unroll
        for (int nt = 0; nt < 4; nt++) {
            int col = wn + nt * 8 + gid;
            bfr[nt][0] = Rs[col * RS2 + kb + tig];
            bfr[nt][1] = Rs[col * RS2 + kb + tig + 4];
        }
#pragma unroll
        for (int mt = 0; mt < 4; mt++) {
            int row = wm + mt * 16 + gid;
            unsigned af[4];
            af[0] = Qs[row * RS2 + kb + tig];
            af[1] = Qs[(row + 8) * RS2 + kb + tig];
            af[2] = Qs[row * RS2 + kb + tig + 4];
            af[3] = Qs[(row + 8) * RS2 + kb + tig + 4];
#pragma unroll
            for (int nt = 0; nt < 4; nt++) mma_tf32(acc[mt][nt], af, bfr[nt]);
        }
    }

    // epilogue: shifted column j = r - T + t, bounds-checked
#pragma unroll
    for (int mt = 0; mt < 4; mt++) {
#pragma unroll
        for (int nt = 0; nt < 4; nt++) {
            int rbase = r0 + wn + nt * 8 + 2 * tig;
#pragma unroll
            for (int half = 0; half < 2; half++) {
                int t = t0 + wm + mt * 16 + gid + half * 8;
                size_t rowbase = ((size_t)bh * T_ + t) * (size_t)L_;
                int j0 = rbase - T_ + t;
                if (j0 >= 0 && j0 < L_) g_rel[rowbase + j0] = acc[mt][nt][half * 2];
                int j1 = j0 + 1;
                if (j1 >= 0 && j1 < L_) g_rel[rowbase + j1] = acc[mt][nt][half * 2 + 1];
            }
        }
    }
}

// ---------------- fused flash attention (tf32 mma) ---------------------------------
// 256 threads = 8 warps. Q-tile 128 rows, j-tile 64. Warp w owns rows [16w, 16w+16),
// all 64 cols; softmax rows never cross warps.
#define FS 68
#define FLASH_SMEM ((128 * FS + 64 * FS + 64 * FS + 128 * FS) * 4)

__global__ __launch_bounds__(256, 2) void k_flash(
    const float* __restrict__ mask, const float* __restrict__ rwb)
{
    extern __shared__ unsigned smu[];
    unsigned* Qs = smu;                       // [t 128][d]  A of S
    unsigned* Ks = smu + 128 * FS;            // [j 64][d]   B of S
    unsigned* Vs = smu + (128 + 64) * FS;     // [j 64][d]   B of PV
    unsigned* Ps = smu + (128 + 128) * FS;    // [t 128][j]  A of PV

    const int tid = threadIdx.x;
    const int lane = tid & 31, warp = tid >> 5;
    const int gid = lane >> 2, tig = lane & 3;
    const int wm = warp * 16;
    const int t0 = blockIdx.x * 128;
    const int h = blockIdx.y;
    const int b = blockIdx.z;
    const int bh = b * H_ + h;

    const int tA = t0 + wm + gid;
    const int tB = tA + 8;
    const float* relA = g_rel + ((size_t)bh * T_ + tA) * (size_t)L_;
    const float* relB = g_rel + ((size_t)bh * T_ + tB) * (size_t)L_;
    const float* mskA = mask + ((size_t)b * T_ + tA) * (size_t)L_;
    const float* mskB = mask + ((size_t)b * T_ + tB) * (size_t)L_;

    // Q tile (128 x 64) + r_w_bias -> tf32 smem
#pragma unroll
    for (int u = 0; u < 8; u++) {
        int idx = tid + u * 256;
        int row = idx >> 4, dq = (idx & 15) << 2;
        float4 qv = *(const float4*)(g_q + (((size_t)bh * T_ + t0 + row) << 6) + dq);
        float4 bv = *(const float4*)(rwb + h * 64 + dq);
        unsigned* qd = &Qs[row * FS + dq];
        qd[0] = f2tf(qv.x + bv.x); qd[1] = f2tf(qv.y + bv.y);
        qd[2] = f2tf(qv.z + bv.z); qd[3] = f2tf(qv.w + bv.w);
    }

    float mA = -CUDART_INF_F, mB = -CUDART_INF_F, lA = 0.f, lB = 0.f;
    float o[8][4];
#pragma unroll
    for (int nt = 0; nt < 8; nt++)
#pragma unroll
        for (int c = 0; c < 4; c++) o[nt][c] = 0.f;

    for (int j0 = 0; j0 < L_; j0 += 64) {
        // stage K and V, both [j][d] (64 x 64 each)
#pragma unroll
        for (int u = 0; u < 4; u++) {
            int idx = tid + u * 256;
            int row = idx >> 4, dq = (idx & 15) << 2;
            float4 kv = *(const float4*)(g_k + (((size_t)bh * L_ + j0 + row) << 6) + dq);
            unsigned* kd = &Ks[row * FS + dq];
            kd[0] = f2tf(kv.x); kd[1] = f2tf(kv.y);
            kd[2] = f2tf(kv.z); kd[3] = f2tf(kv.w);
            float4 vv = *(const float4*)(g_v + (((size_t)bh * L_ + j0 + row) << 6) + dq);
            unsigned* vd = &Vs[row * FS + dq];
            vd[0] = f2tf(vv.x); vd[1] = f2tf(vv.y);
            vd[2] = f2tf(vv.z); vd[3] = f2tf(vv.w);
        }
        __syncthreads();

        // S = Q K^T  (warp: 16 rows x 64 cols)
        float s[8][4];
#pragma unroll
        for (int nt = 0; nt < 8; nt++)
#pragma unroll
            for (int c = 0; c < 4; c++) s[nt][c] = 0.f;
#pragma unroll
        for (int ks = 0; ks < 8; ks++) {
            const int kb = ks * 8;
            unsigned af[4];
            af[0] = Qs[(wm + gid) * FS + kb + tig];
            af[1] = Qs[(wm + gid + 8) * FS + kb + tig];
            af[2] = Qs[(wm + gid) * FS + kb + tig + 4];
            af[3] = Qs[(wm + gid + 8) * FS + kb + tig + 4];
#pragma unroll
            for (int nt = 0; nt < 8; nt++) {
                unsigned bf[2];
                bf[0] = Ks[(nt * 8 + gid) * FS + kb + tig];
                bf[1] = Ks[(nt * 8 + gid) * FS + kb + tig + 4];
                mma_tf32(s[nt], af, bf);
            }
        }

        // + rel, * scale, mask
#pragma unroll
        for (int nt = 0; nt < 8; nt++) {
            int c = j0 + nt * 8 + 2 * tig;
            float2 ra = *(const float2*)(relA + c);
            float2 rb = *(const float2*)(relB + c);
            float2 ma = *(const float2*)(mskA + c);
            float2 mb = *(const float2*)(mskB + c);
            s[nt][0] = (s[nt][0] + ra.x) * 0.125f - (1.f - ma.x) * 1e30f;
            s[nt][1] = (s[nt][1] + ra.y) * 0.125f - (1.f - ma.y) * 1e30f;
            s[nt][2] = (s[nt][2] + rb.x) * 0.125f - (1.f - mb.x) * 1e30f;
            s[nt][3] = (s[nt][3] + rb.y) * 0.125f - (1.f - mb.y) * 1e30f;
        }

        // online softmax (rows A=gid, B=gid+8; reduce over the 4 tig lanes)
        float mxA = -CUDART_INF_F, mxB = -CUDART_INF_F;
#pragma unroll
        for (int nt = 0; nt < 8; nt++) {
            mxA = fmaxf(mxA, fmaxf(s[nt][0], s[nt][1]));
            mxB = fmaxf(mxB, fmaxf(s[nt][2], s[nt][3]));
        }
        mxA = fmaxf(mxA, __shfl_xor_sync(0xffffffffu, mxA, 1));
        mxA = fmaxf(mxA, __shfl_xor_sync(0xffffffffu, mxA, 2));
        mxB = fmaxf(mxB, __shfl_xor_sync(0xffffffffu, mxB, 1));
        mxB = fmaxf(mxB, __shfl_xor_sync(0xffffffffu, mxB, 2));

        float mnA = fmaxf(mA, mxA), mnB = fmaxf(mB, mxB);
        float aA = __expf(mA - mnA), aB = __expf(mB - mnB);
        float rsA = 0.f, rsB = 0.f;
#pragma unroll
        for (int nt = 0; nt < 8; nt++) {
            // round P to tf32 so l matches the weights PV actually uses
            float p0 = __uint_as_float(f2tf(__expf(s[nt][0] - mnA)));
            float p1 = __uint_as_float(f2tf(__expf(s[nt][1] - mnA)));
            float p2 = __uint_as_float(f2tf(__expf(s[nt][2] - mnB)));
            float p3 = __uint_as_float(f2tf(__expf(s[nt][3] - mnB)));
            s[nt][0] = p0; s[nt][1] = p1; s[nt][2] = p2; s[nt][3] = p3;
            rsA += p0 + p1; rsB += p2 + p3;
        }
        rsA += __shfl_xor_sync(0xffffffffu, rsA, 1);
        rsA += __shfl_xor_sync(0xffffffffu, rsA, 2);
        rsB += __shfl_xor_sync(0xffffffffu, rsB, 1);
        rsB += __shfl_xor_sync(0xffffffffu, rsB, 2);
        mA = mnA; mB = mnB;
        lA = lA * aA + rsA; lB = lB * aB + rsB;
#pragma unroll
        for (int nt = 0; nt < 8; nt++) {
            o[nt][0] *= aA; o[nt][1] *= aA;
            o[nt][2] *= aB; o[nt][3] *= aB;
        }

        // P -> smem (A-operand layout); warp reads only rows it wrote -> warpsync
#pragma unroll
        for (int nt = 0; nt < 8; nt++) {
            int cc = nt * 8 + 2 * tig;
            Ps[(wm + gid) * FS + cc]     = __float_as_uint(s[nt][0]);
            Ps[(wm + gid) * FS + cc + 1] = __float_as_uint(s[nt][1]);
            Ps[(wm + gid + 8) * FS + cc]     = __float_as_uint(s[nt][2]);
            Ps[(wm + gid + 8) * FS + cc + 1] = __float_as_uint(s[nt][3]);
        }
        __syncwarp();

        // O += P V   (B fragment from Vs[j][d])
#pragma unroll
        for (int ks = 0; ks < 8; ks++) {
            const int kb = ks * 8;
            unsigned af[4];
            af[0] = Ps[(wm + gid) * FS + kb + tig];
            af[1] = Ps[(wm + gid + 8) * FS + kb + tig];
            af[2] = Ps[(wm + gid) * FS + kb + tig + 4];
            af[3] = Ps[(wm + gid + 8) * FS + kb + tig + 4];
#pragma unroll
            for (int nt = 0; nt < 8; nt++) {
                unsigned bf[2];
                bf[0] = Vs[(kb + tig) * FS + nt * 8 + gid];
                bf[1] = Vs[(kb + tig + 4) * FS + nt * 8 + gid];
                mma_tf32(o[nt], af, bf);
            }
        }
        __syncthreads();   // protect Ks/Vs before next stage
    }

    // normalize + write attn [B*T, H*64]
    float invA = 1.f / lA, invB = 1.f / lB;
#pragma unroll
    for (int nt = 0; nt < 8; nt++) {
        int col = h * 64 + nt * 8 + 2 * tig;
        *(float2*)(g_attn + (((size_t)b * T_ + tA) << 10) + col) =
            make_float2(o[nt][0] * invA, o[nt][1] * invA);
        *(float2*)(g_attn + (((size_t)b * T_ + tB) << 10) + col) =
            make_float2(o[nt][2] * invB, o[nt][3] * invB);
    }
}

// ---------------- launch ------------------------------------------------------------
extern "C" void kernel_launch(void* const* d_in, const int* in_sizes, int n_in,
                              void* d_out, int out_size)
{
    (void)in_sizes; (void)n_in; (void)out_size;
    const float* inputs = (const float*)d_in[0];
    const float* mask   = (const float*)d_in[1];
    const float* pos    = (const float*)d_in[2];
    const float* mem    = (const float*)d_in[3];
    const float* Wq     = (const float*)d_in[4];
    const float* Wk     = (const float*)d_in[5];
    const float* Wv     = (const float*)d_in[6];
    const float* Wr     = (const float*)d_in[7];
    const float* rwb    = (const float*)d_in[8];
    const float* rrb    = (const float*)d_in[9];
    const float* Wout   = (const float*)d_in[10];
    float* out = (float*)d_out;

    cudaFuncSetAttribute(k_proj_all, cudaFuncAttributeMaxDynamicSharedMemorySize, GEMM_SMEM);
    cudaFuncSetAttribute(k_out,      cudaFuncAttributeMaxDynamicSharedMemorySize, GEMM_SMEM);
    cudaFuncSetAttribute(k_relgemm,  cudaFuncAttributeMaxDynamicSharedMemorySize, REL_SMEM);
    cudaFuncSetAttribute(k_flash,    cudaFuncAttributeMaxDynamicSharedMemorySize, FLASH_SMEM);

    k_proj_all<<<832, 256, GEMM_SMEM>>>(inputs, mem, pos, Wq, Wk, Wv, Wr);

    k_relgemm<<<dim3(R_ / 128, T_ / 128, B_ * H_), 256, REL_SMEM>>>(rrb);

    k_flash<<<dim3(T_ / 128, H_, B_), 256, FLASH_SMEM>>>(mask, rwb);

    k_out<<<dim3(8, (B_ * T_) / 128), 256, GEMM_SMEM>>>(Wout, out);
}